// round 8
// baseline (speedup 1.0000x reference)
#include <cuda_runtime.h>
#include <cuda_fp16.h>
#include <mma.h>
#include <cstdint>

using namespace nvcuda;

// Problem constants (fixed shapes)
#define DMODEL 1024
#define SEQ    2048
#define NB     4
#define MT     (NB * SEQ)   // 8192 total rows

// ---------------- scratch (device globals; no allocation allowed) -----------
__device__ unsigned short g_hRQ[(size_t)MT * DMODEL];        // inputQ (half)
__device__ unsigned short g_hRK[(size_t)MT * DMODEL];        // inputK (half)
__device__ unsigned short g_hRV[(size_t)MT * DMODEL];        // inputV (half)
__device__ unsigned short g_hW4[4][(size_t)DMODEL * DMODEL]; // WQ,WK,WV,WO (half)
__device__ unsigned short g_hQ[(size_t)MT * DMODEL];         // proj Q (half)
__device__ unsigned short g_hK[(size_t)MT * DMODEL];         // proj K (half)
__device__ unsigned short g_hV[(size_t)MT * DMODEL];         // proj V (half)
__device__ unsigned short g_hA[(size_t)NB * SEQ * SEQ];      // attn (half)
__device__ unsigned short g_hWv[(size_t)MT * DMODEL];        // attn@V (half)
__device__ float g_S[(size_t)NB * SEQ * SEQ];                // masked scaled scores
__device__ float g_P[(size_t)MT * DMODEL];                   // out proj (fp32)

// ---------------- fp16 WMMA GEMM, cp.async 4-stage ---------------------------
// C[M,N] = A[M,K] * op(B); A,B are __half row-major.
// BT=true: B is [N,K] (C = A*B^T); BT=false: B is [K,N].
// EPI: 0 = fp32 direct store, 1 = fp16 staged store,
//      2 = masked+scaled fp32 staged store (scores epilogue).
// 128x256 CTA tile, 64x64 warp tiles (8 warps) -> smem-BW balanced:
// ~0.084 B/MAC of L1 traffic vs 128 B/cyc crossbar.
constexpr int BM = 128, BN = 256, BK = 32;
constexpr int KP = 40;    // padded smem K stride (halves); 80 B rows
constexpr int NP = 264;   // padded smem N stride (halves) for NN B tile
constexpr int STG = 4;
constexpr int ASZ   = BM * KP;    // 5120 halves per A stage
constexpr int BSZ_T = BN * KP;    // 10240 halves per NT B stage
constexpr int BSZ_N = BK * NP;    // 8448 halves per NN B stage
constexpr int GSMEM = 131072;     // pipeline (122880) and fp32 staging (131072)

__device__ __forceinline__ void cp16(uint32_t saddr, const void* gptr) {
    asm volatile("cp.async.cg.shared.global [%0], [%1], 16;\n"
                 :: "r"(saddr), "l"(gptr) : "memory");
}
__device__ __forceinline__ void cp_commit() {
    asm volatile("cp.async.commit_group;\n" ::: "memory");
}

template <bool BT, int EPI>
__global__ __launch_bounds__(256, 1) void gemm_h(
    const __half* __restrict__ A, const __half* __restrict__ Bm,
    void* __restrict__ Cv, const int* __restrict__ mask,
    int N, int K, long long sA, long long sB, long long sC)
{
    A  += (long long)blockIdx.z * sA;
    Bm += (long long)blockIdx.z * sB;

    extern __shared__ __half sm[];
    constexpr int BSZ = BT ? BSZ_T : BSZ_N;
    __half* As = sm;
    __half* Bs = sm + STG * ASZ;

    const int t   = threadIdx.x;
    const int w   = t >> 5;
    const int lid = t & 31;
    const int wm  = (w >> 2) * 64;   // 2 warps along M
    const int wn  = (w & 3) * 64;    // 4 warps along N
    const int bm  = blockIdx.y * BM;
    const int bn  = blockIdx.x * BN;

    const uint32_t as_base = (uint32_t)__cvta_generic_to_shared(As);
    const uint32_t bs_base = (uint32_t)__cvta_generic_to_shared(Bs);

    auto load_stage = [&](int s, int k0) {
        uint32_t ab = as_base + (uint32_t)(s * ASZ) * 2u;
        uint32_t bb = bs_base + (uint32_t)(s * BSZ) * 2u;
        // A tile: 128 rows x 32 halves -> 512 cp16 (2 per thread)
#pragma unroll
        for (int i = 0; i < 2; i++) {
            int idx = t + i * 256;
            int r = idx >> 2, c8 = (idx & 3) << 3;
            cp16(ab + (uint32_t)(r * KP + c8) * 2u,
                 &A[(long long)(bm + r) * K + k0 + c8]);
        }
        if constexpr (BT) {
            // B tile: 256 n-rows x 32 halves -> 1024 cp16 (4 per thread)
#pragma unroll
            for (int i = 0; i < 4; i++) {
                int idx = t + i * 256;
                int r = idx >> 2, c8 = (idx & 3) << 3;
                cp16(bb + (uint32_t)(r * KP + c8) * 2u,
                     &Bm[(long long)(bn + r) * K + k0 + c8]);
            }
        } else {
            // B tile: 32 k-rows x 256 halves -> 1024 cp16
#pragma unroll
            for (int i = 0; i < 4; i++) {
                int idx = t + i * 256;
                int r = idx >> 5, c8 = (idx & 31) << 3;
                cp16(bb + (uint32_t)(r * NP + c8) * 2u,
                     &Bm[(long long)(k0 + r) * N + bn + c8]);
            }
        }
    };

    wmma::fragment<wmma::accumulator, 16, 16, 16, float> cf[4][4];
#pragma unroll
    for (int i = 0; i < 4; i++)
#pragma unroll
        for (int j = 0; j < 4; j++) wmma::fill_fragment(cf[i][j], 0.0f);

    const int KT = K / BK;

#pragma unroll
    for (int s = 0; s < STG - 1; s++) { load_stage(s, s * BK); cp_commit(); }

    for (int kt = 0; kt < KT; kt++) {
        asm volatile("cp.async.wait_group 2;\n" ::: "memory");
        __syncthreads();

        int f = kt + STG - 1;
        if (f < KT) load_stage(f & (STG - 1), f * BK);
        cp_commit();

        const __half* Asw = As + (kt & (STG - 1)) * ASZ;
        const __half* Bsw = Bs + (kt & (STG - 1)) * BSZ;

#pragma unroll
        for (int ks = 0; ks < BK; ks += 16) {
            wmma::fragment<wmma::matrix_a, 16, 16, 16, __half, wmma::row_major> af[4];
#pragma unroll
            for (int i = 0; i < 4; i++)
                wmma::load_matrix_sync(af[i], &Asw[(wm + i * 16) * KP + ks], KP);

            if constexpr (BT) {
                wmma::fragment<wmma::matrix_b, 16, 16, 16, __half, wmma::col_major> bf[4];
#pragma unroll
                for (int j = 0; j < 4; j++)
                    wmma::load_matrix_sync(bf[j], &Bsw[(wn + j * 16) * KP + ks], KP);
#pragma unroll
                for (int i = 0; i < 4; i++)
#pragma unroll
                    for (int j = 0; j < 4; j++)
                        wmma::mma_sync(cf[i][j], af[i], bf[j], cf[i][j]);
            } else {
                wmma::fragment<wmma::matrix_b, 16, 16, 16, __half, wmma::row_major> bf[4];
#pragma unroll
                for (int j = 0; j < 4; j++)
                    wmma::load_matrix_sync(bf[j], &Bsw[ks * NP + wn + j * 16], NP);
#pragma unroll
                for (int i = 0; i < 4; i++)
#pragma unroll
                    for (int j = 0; j < 4; j++)
                        wmma::mma_sync(cf[i][j], af[i], bf[j], cf[i][j]);
            }
        }
    }

    if constexpr (EPI == 0) {
        float* Cf = (float*)Cv + (long long)blockIdx.z * sC;
#pragma unroll
        for (int i = 0; i < 4; i++)
#pragma unroll
            for (int j = 0; j < 4; j++)
                wmma::store_matrix_sync(
                    &Cf[(long long)(bm + wm + i * 16) * N + bn + wn + j * 16],
                    cf[i][j], N, wmma::mem_row_major);
    } else {
        // stage fp32 accumulators in (reused) smem, 64x64 per warp
        __syncthreads();
        float* stg = (float*)sm + (size_t)w * 4096;
#pragma unroll
        for (int i = 0; i < 4; i++)
#pragma unroll
            for (int j = 0; j < 4; j++)
                wmma::store_matrix_sync(&stg[(i * 16) * 64 + j * 16], cf[i][j],
                                        64, wmma::mem_row_major);
        __syncwarp();
        if constexpr (EPI == 1) {
            __half* Ch = (__half*)Cv + (long long)blockIdx.z * sC;
#pragma unroll
            for (int k = 0; k < 16; k++) {
                int idx = lid + k * 32;          // 512 chunks of 8 halves
                int r = idx >> 3, cc = (idx & 7) << 3;
                const float* src = &stg[r * 64 + cc];
                __half2 h0 = __floats2half2_rn(src[0], src[1]);
                __half2 h1 = __floats2half2_rn(src[2], src[3]);
                __half2 h2 = __floats2half2_rn(src[4], src[5]);
                __half2 h3 = __floats2half2_rn(src[6], src[7]);
                uint4 u;
                u.x = *(uint32_t*)&h0; u.y = *(uint32_t*)&h1;
                u.z = *(uint32_t*)&h2; u.w = *(uint32_t*)&h3;
                *(uint4*)&Ch[(long long)(bm + wm + r) * N + bn + wn + cc] = u;
            }
        } else {
            // EPI == 2: masked + scaled fp32 store (scores epilogue)
            float* Cf = (float*)Cv + (long long)blockIdx.z * sC;
            const int* Mb = mask + (long long)blockIdx.z * sC;
#pragma unroll
            for (int it = 0; it < 128; it++) {
                int g = it * 32 + lid;            // 4096 floats per warp
                int r = g >> 6, cc = g & 63;
                long long gi = (long long)(bm + wm + r) * N + bn + wn + cc;
                float s = stg[r * 64 + cc] * 0.125f;
                if (Mb[gi] == 1) s = -1e9f;
                Cf[gi] = s;
            }
        }
    }
}

// ---------------- fused fp32 -> fp16 converts ---------------------------------
__global__ __launch_bounds__(256) void f2h3(
    const float* __restrict__ x0, const float* __restrict__ x1,
    const float* __restrict__ x2,
    __half* __restrict__ y0, __half* __restrict__ y1, __half* __restrict__ y2,
    int n4)
{
    const float* x = (blockIdx.y == 0) ? x0 : (blockIdx.y == 1) ? x1 : x2;
    __half*      y = (blockIdx.y == 0) ? y0 : (blockIdx.y == 1) ? y1 : y2;
    int i = blockIdx.x * 256 + threadIdx.x;
    if (i < n4) {
        float4 v = ((const float4*)x)[i];
        __half2 a = __floats2half2_rn(v.x, v.y);
        __half2 b = __floats2half2_rn(v.z, v.w);
        uint2 u; u.x = *(uint32_t*)&a; u.y = *(uint32_t*)&b;
        ((uint2*)y)[i] = u;
    }
}

__global__ __launch_bounds__(256) void f2h4(
    const float* __restrict__ x0, const float* __restrict__ x1,
    const float* __restrict__ x2, const float* __restrict__ x3,
    __half* __restrict__ y, int n4)   // y: 4 consecutive DMODEL^2 blocks
{
    const float* x = (blockIdx.y == 0) ? x0 : (blockIdx.y == 1) ? x1
                   : (blockIdx.y == 2) ? x2 : x3;
    __half* yo = y + (size_t)blockIdx.y * DMODEL * DMODEL;
    int i = blockIdx.x * 256 + threadIdx.x;
    if (i < n4) {
        float4 v = ((const float4*)x)[i];
        __half2 a = __floats2half2_rn(v.x, v.y);
        __half2 b = __floats2half2_rn(v.z, v.w);
        uint2 u; u.x = *(uint32_t*)&a; u.y = *(uint32_t*)&b;
        ((uint2*)yo)[i] = u;
    }
}

// ---------------- softmax over pre-masked scaled rows -> fp16 -----------------
__global__ __launch_bounds__(256) void softmax_rows(
    const float* __restrict__ S, __half* __restrict__ Ao)
{
    const long long row = blockIdx.x;
    const float* sr = S + row * (long long)SEQ;
    __half* ar = Ao + row * (long long)SEQ;
    const int t = threadIdx.x;

    float v[8];
    float mx = -3.0e38f;
#pragma unroll
    for (int i = 0; i < 8; i++) {
        v[i] = sr[t + i * 256];
        mx = fmaxf(mx, v[i]);
    }

    __shared__ float red[8];
#pragma unroll
    for (int o = 16; o; o >>= 1) mx = fmaxf(mx, __shfl_xor_sync(~0u, mx, o));
    if ((t & 31) == 0) red[t >> 5] = mx;
    __syncthreads();
    mx = red[0];
#pragma unroll
    for (int i = 1; i < 8; i++) mx = fmaxf(mx, red[i]);

    float sum = 0.f;
#pragma unroll
    for (int i = 0; i < 8; i++) {
        v[i] = exp2f((v[i] - mx) * 1.4426950408889634f);
        sum += v[i];
    }
#pragma unroll
    for (int o = 16; o; o >>= 1) sum += __shfl_xor_sync(~0u, sum, o);
    __syncthreads();
    if ((t & 31) == 0) red[t >> 5] = sum;
    __syncthreads();
    sum = 0.f;
#pragma unroll
    for (int i = 0; i < 8; i++) sum += red[i];
    float inv = 1.0f / sum;
#pragma unroll
    for (int i = 0; i < 8; i++) ar[t + i * 256] = __float2half_rn(v[i] * inv);
}

// ---------------- residual add + LayerNorm -----------------------------------
__global__ __launch_bounds__(256) void add_layernorm(
    const float* __restrict__ P, const float* __restrict__ R,
    const float* __restrict__ gamma, const float* __restrict__ beta,
    float* __restrict__ O)
{
    const long long row = blockIdx.x;
    const float* pr = P + row * (long long)DMODEL;
    const float* rr = R + row * (long long)DMODEL;
    float* orow = O + row * (long long)DMODEL;
    const int t = threadIdx.x;

    float x[4];
    float s = 0.f;
#pragma unroll
    for (int i = 0; i < 4; i++) {
        int c = t + i * 256;
        x[i] = pr[c] + rr[c];
        s += x[i];
    }

    __shared__ float red[8];
#pragma unroll
    for (int o = 16; o; o >>= 1) s += __shfl_xor_sync(~0u, s, o);
    if ((t & 31) == 0) red[t >> 5] = s;
    __syncthreads();
    s = 0.f;
#pragma unroll
    for (int i = 0; i < 8; i++) s += red[i];
    const float mu = s * (1.0f / DMODEL);

    float vq = 0.f;
#pragma unroll
    for (int i = 0; i < 4; i++) {
        float d = x[i] - mu;
        vq += d * d;
    }
#pragma unroll
    for (int o = 16; o; o >>= 1) vq += __shfl_xor_sync(~0u, vq, o);
    __syncthreads();
    if ((t & 31) == 0) red[t >> 5] = vq;
    __syncthreads();
    vq = 0.f;
#pragma unroll
    for (int i = 0; i < 8; i++) vq += red[i];
    const float rs = rsqrtf(vq * (1.0f / DMODEL) + 1e-5f);

#pragma unroll
    for (int i = 0; i < 4; i++) {
        int c = t + i * 256;
        orow[c] = (x[i] - mu) * rs * gamma[c] + beta[c];
    }
}

// ---------------- launch ------------------------------------------------------
extern "C" void kernel_launch(void* const* d_in, const int* in_sizes, int n_in,
                              void* d_out, int out_size)
{
    (void)in_sizes; (void)n_in; (void)out_size;
    const float* inQ  = (const float*)d_in[0];
    const float* inK  = (const float*)d_in[1];
    const float* inV  = (const float*)d_in[2];
    const int*   mask = (const int*)  d_in[3];
    const float* WQ   = (const float*)d_in[4];
    const float* WK   = (const float*)d_in[5];
    const float* WV   = (const float*)d_in[6];
    const float* WO   = (const float*)d_in[7];
    const float* gam  = (const float*)d_in[8];
    const float* bet  = (const float*)d_in[9];
    float* out = (float*)d_out;

    void *pRQ, *pRK, *pRV, *pW4, *pQ, *pK, *pV, *pA, *pWv, *pS, *pP;
    cudaGetSymbolAddress(&pRQ, g_hRQ);
    cudaGetSymbolAddress(&pRK, g_hRK);
    cudaGetSymbolAddress(&pRV, g_hRV);
    cudaGetSymbolAddress(&pW4, g_hW4);
    cudaGetSymbolAddress(&pQ,  g_hQ);
    cudaGetSymbolAddress(&pK,  g_hK);
    cudaGetSymbolAddress(&pV,  g_hV);
    cudaGetSymbolAddress(&pA,  g_hA);
    cudaGetSymbolAddress(&pWv, g_hWv);
    cudaGetSymbolAddress(&pS,  g_S);
    cudaGetSymbolAddress(&pP,  g_P);
    __half* hRQ = (__half*)pRQ;
    __half* hRK = (__half*)pRK;
    __half* hRV = (__half*)pRV;
    __half* hWQ = (__half*)pW4;
    __half* hWK = hWQ + (size_t)DMODEL * DMODEL;
    __half* hWV = hWQ + 2 * (size_t)DMODEL * DMODEL;
    __half* hWO = hWQ + 3 * (size_t)DMODEL * DMODEL;
    __half* hQ  = (__half*)pQ;
    __half* hK  = (__half*)pK;
    __half* hV  = (__half*)pV;
    __half* hA  = (__half*)pA;
    __half* hWv = (__half*)pWv;
    float*  S   = (float*)pS;
    float*  P   = (float*)pP;

    cudaFuncSetAttribute(gemm_h<true, 1>,
                         cudaFuncAttributeMaxDynamicSharedMemorySize, GSMEM);
    cudaFuncSetAttribute(gemm_h<true, 0>,
                         cudaFuncAttributeMaxDynamicSharedMemorySize, GSMEM);
    cudaFuncSetAttribute(gemm_h<true, 2>,
                         cudaFuncAttributeMaxDynamicSharedMemorySize, GSMEM);
    cudaFuncSetAttribute(gemm_h<false, 1>,
                         cudaFuncAttributeMaxDynamicSharedMemorySize, GSMEM);

    const dim3 blk(256);
    const long long sQK = (long long)SEQ * DMODEL;
    const long long sSS = (long long)SEQ * SEQ;

    // launch 1-2: fused fp32 -> fp16 converts
    const int nBig4 = MT * DMODEL / 4;
    const int nW4   = DMODEL * DMODEL / 4;
    f2h3<<<dim3((nBig4 + 255) / 256, 3), 256>>>(inQ, inK, inV, hRQ, hRK, hRV, nBig4);
    f2h4<<<dim3((nW4 + 255) / 256, 4), 256>>>(WQ, WK, WV, WO, hWQ, nW4);

    // launches 3-5: projections [8192,1024] = X * W^T -> half
    gemm_h<true, 1><<<dim3(DMODEL / BN, MT / BM, 1), blk, GSMEM>>>(
        hRQ, hWQ, hQ, nullptr, DMODEL, DMODEL, 0, 0, 0);
    gemm_h<true, 1><<<dim3(DMODEL / BN, MT / BM, 1), blk, GSMEM>>>(
        hRK, hWK, hK, nullptr, DMODEL, DMODEL, 0, 0, 0);
    gemm_h<true, 1><<<dim3(DMODEL / BN, MT / BM, 1), blk, GSMEM>>>(
        hRV, hWV, hV, nullptr, DMODEL, DMODEL, 0, 0, 0);

    // launch 6 (ncu target): scores = Q*K^T with fused mask+scale -> fp32
    gemm_h<true, 2><<<dim3(SEQ / BN, SEQ / BM, NB), blk, GSMEM>>>(
        hQ, hK, S, mask, SEQ, DMODEL, sQK, sQK, sSS);

    // softmax over pre-masked rows -> fp16 attn
    softmax_rows<<<NB * SEQ, 256>>>(S, hA);

    // attn @ V: per batch [2048,1024] = A * V (NN) -> half
    gemm_h<false, 1><<<dim3(DMODEL / BN, SEQ / BM, NB), blk, GSMEM>>>(
        hA, hV, hWv, nullptr, DMODEL, SEQ, sSS, sQK, sQK);

    // out proj: [8192,1024] = W * WO^T -> fp32
    gemm_h<true, 0><<<dim3(DMODEL / BN, MT / BM, 1), blk, GSMEM>>>(
        hWv, hWO, P, nullptr, DMODEL, DMODEL, 0, 0, 0);

    // residual + layernorm -> d_out
    add_layernorm<<<MT, 256>>>(P, inQ, gam, bet, out);
}

// round 9
// speedup vs baseline: 1.1683x; 1.1683x over previous
#include <cuda_runtime.h>
#include <cuda_fp16.h>
#include <mma.h>
#include <cstdint>

using namespace nvcuda;

// Problem constants (fixed shapes)
#define DMODEL 1024
#define SEQ    2048
#define NB     4
#define MT     (NB * SEQ)   // 8192 total rows

// ---------------- scratch (device globals; no allocation allowed) -----------
// Contiguous layouts so Q/K/V projections run as ONE batched GEMM (z=0..2).
__device__ unsigned short g_hIN[3][(size_t)MT * DMODEL];     // inQ,inK,inV (half)
__device__ unsigned short g_hW4[4][(size_t)DMODEL * DMODEL]; // WQ,WK,WV,WO (half)
__device__ unsigned short g_hQKV[3][(size_t)MT * DMODEL];    // projQ,K,V (half)
__device__ unsigned short g_hA[(size_t)NB * SEQ * SEQ];      // attn (half)
__device__ unsigned short g_hWv[(size_t)MT * DMODEL];        // attn@V (half)
__device__ float g_S[(size_t)NB * SEQ * SEQ];                // masked scaled scores
__device__ float g_P[(size_t)MT * DMODEL];                   // out proj (fp32)

// ---------------- fp16 WMMA GEMM, cp.async 5-stage, 2 CTAs/SM ----------------
// C[M,N] = A[M,K] * op(B); A,B are __half row-major; batched via blockIdx.z
// with strides sA/sB/sC. BT=true: B is [N,K] (C=A*B^T); BT=false: B is [K,N].
// EPI: 0 = fp32 direct store, 1 = fp16 staged store,
//      2 = masked+scaled fp32 staged store (scores epilogue).
constexpr int BM = 128, BN = 128, BK = 32;
constexpr int KP = 40;    // padded smem K stride (halves); 80 B rows
constexpr int NP = 136;   // padded smem N stride (halves) for NN B tile
constexpr int STG = 5;
constexpr int ASZ   = BM * KP;    // 5120 halves per A stage
constexpr int BSZ_T = BN * KP;    // 5120 halves per NT B stage
constexpr int BSZ_N = BK * NP;    // 4352 halves per NN B stage
constexpr int GSMEM = STG * (ASZ + BSZ_T) * 2;   // 102400 B; 2 CTAs fit 228KB

__device__ __forceinline__ void cp16(uint32_t saddr, const void* gptr) {
    asm volatile("cp.async.cg.shared.global [%0], [%1], 16;\n"
                 :: "r"(saddr), "l"(gptr) : "memory");
}
__device__ __forceinline__ void cp_commit() {
    asm volatile("cp.async.commit_group;\n" ::: "memory");
}

template <bool BT, int EPI>
__global__ __launch_bounds__(256, 2) void gemm_h(
    const __half* __restrict__ A, const __half* __restrict__ Bm,
    void* __restrict__ Cv, const int* __restrict__ mask,
    int N, int K, long long sA, long long sB, long long sC)
{
    A  += (long long)blockIdx.z * sA;
    Bm += (long long)blockIdx.z * sB;

    extern __shared__ __half sm[];
    constexpr int BSZ = BT ? BSZ_T : BSZ_N;
    __half* As = sm;
    __half* Bs = sm + STG * ASZ;

    const int t   = threadIdx.x;
    const int w   = t >> 5;
    const int lid = t & 31;
    const int wm  = (w >> 2) * 64;   // 2 warps along M
    const int wn  = (w & 3) * 32;    // 4 warps along N
    const int bm  = blockIdx.y * BM;
    const int bn  = blockIdx.x * BN;

    const uint32_t as_base = (uint32_t)__cvta_generic_to_shared(As);
    const uint32_t bs_base = (uint32_t)__cvta_generic_to_shared(Bs);

    auto load_stage = [&](int s, int k0) {
        uint32_t ab = as_base + (uint32_t)(s * ASZ) * 2u;
        uint32_t bb = bs_base + (uint32_t)(s * BSZ) * 2u;
        // A tile: 128 rows x 32 halves -> 512 cp16 (2 per thread)
#pragma unroll
        for (int i = 0; i < 2; i++) {
            int idx = t + i * 256;
            int r = idx >> 2, c8 = (idx & 3) << 3;
            cp16(ab + (uint32_t)(r * KP + c8) * 2u,
                 &A[(long long)(bm + r) * K + k0 + c8]);
        }
        if constexpr (BT) {
            // B tile: 128 n-rows x 32 halves
#pragma unroll
            for (int i = 0; i < 2; i++) {
                int idx = t + i * 256;
                int r = idx >> 2, c8 = (idx & 3) << 3;
                cp16(bb + (uint32_t)(r * KP + c8) * 2u,
                     &Bm[(long long)(bn + r) * K + k0 + c8]);
            }
        } else {
            // B tile: 32 k-rows x 128 halves
#pragma unroll
            for (int i = 0; i < 2; i++) {
                int idx = t + i * 256;
                int r = idx >> 4, c8 = (idx & 15) << 3;
                cp16(bb + (uint32_t)(r * NP + c8) * 2u,
                     &Bm[(long long)(k0 + r) * N + bn + c8]);
            }
        }
    };

    wmma::fragment<wmma::accumulator, 16, 16, 16, float> cf[4][2];
#pragma unroll
    for (int i = 0; i < 4; i++)
#pragma unroll
        for (int j = 0; j < 2; j++) wmma::fill_fragment(cf[i][j], 0.0f);

    // one k-step (K=16) of fragment loads + 8 MMAs
    auto compute_ks = [&](const __half* Asw, const __half* Bsw, int ks) {
        wmma::fragment<wmma::matrix_a, 16, 16, 16, __half, wmma::row_major> af[4];
#pragma unroll
        for (int i = 0; i < 4; i++)
            wmma::load_matrix_sync(af[i], &Asw[(wm + i * 16) * KP + ks], KP);
        if constexpr (BT) {
            wmma::fragment<wmma::matrix_b, 16, 16, 16, __half, wmma::col_major> bf[2];
#pragma unroll
            for (int j = 0; j < 2; j++)
                wmma::load_matrix_sync(bf[j], &Bsw[(wn + j * 16) * KP + ks], KP);
#pragma unroll
            for (int i = 0; i < 4; i++)
#pragma unroll
                for (int j = 0; j < 2; j++)
                    wmma::mma_sync(cf[i][j], af[i], bf[j], cf[i][j]);
        } else {
            wmma::fragment<wmma::matrix_b, 16, 16, 16, __half, wmma::row_major> bf[2];
#pragma unroll
            for (int j = 0; j < 2; j++)
                wmma::load_matrix_sync(bf[j], &Bsw[ks * NP + wn + j * 16], NP);
#pragma unroll
            for (int i = 0; i < 4; i++)
#pragma unroll
                for (int j = 0; j < 2; j++)
                    wmma::mma_sync(cf[i][j], af[i], bf[j], cf[i][j]);
        }
    };

    const int KT = K / BK;

#pragma unroll
    for (int s = 0; s < STG - 1; s++) { load_stage(s, s * BK); cp_commit(); }

    for (int kt = 0; kt < KT; kt++) {
        asm volatile("cp.async.wait_group 3;\n" ::: "memory");
        __syncthreads();

        const int si = kt % STG;
        const __half* Asw = As + si * ASZ;
        const __half* Bsw = Bs + si * BSZ;

        // tensor work first: MMAs for ks=0 start right after the barrier
        compute_ks(Asw, Bsw, 0);

        // then issue next stage's async loads (overlap with ks=1 compute)
        int f = kt + STG - 1;
        if (f < KT) load_stage(f % STG, f * BK);
        cp_commit();

        compute_ks(Asw, Bsw, 16);
    }

    if constexpr (EPI == 0) {
        float* Cf = (float*)Cv + (long long)blockIdx.z * sC;
#pragma unroll
        for (int i = 0; i < 4; i++)
#pragma unroll
            for (int j = 0; j < 2; j++)
                wmma::store_matrix_sync(
                    &Cf[(long long)(bm + wm + i * 16) * N + bn + wn + j * 16],
                    cf[i][j], N, wmma::mem_row_major);
    } else {
        // stage fp32 accumulators in (reused) smem, 64x32 per warp
        __syncthreads();
        float* stg = (float*)sm + (size_t)w * 2048;
#pragma unroll
        for (int i = 0; i < 4; i++)
#pragma unroll
            for (int j = 0; j < 2; j++)
                wmma::store_matrix_sync(&stg[(i * 16) * 32 + j * 16], cf[i][j],
                                        32, wmma::mem_row_major);
        __syncwarp();
        if constexpr (EPI == 1) {
            __half* Ch = (__half*)Cv + (long long)blockIdx.z * sC;
#pragma unroll
            for (int it = 0; it < 32; it++) {
                int g = it * 32 + lid;            // 1024 half2 chunks
                int r = g >> 4, cp = (g & 15) << 1;
                float2 v = *(const float2*)&stg[r * 32 + cp];
                __half2 h = __floats2half2_rn(v.x, v.y);
                *(__half2*)&Ch[(long long)(bm + wm + r) * N + bn + wn + cp] = h;
            }
        } else {
            // EPI == 2: masked + scaled fp32 store (scores epilogue)
            float* Cf = (float*)Cv + (long long)blockIdx.z * sC;
            const int* Mb = mask + (long long)blockIdx.z * sC;
#pragma unroll
            for (int it = 0; it < 64; it++) {
                int g = it * 32 + lid;            // 2048 floats
                int r = g >> 5, cc = g & 31;
                long long gi = (long long)(bm + wm + r) * N + bn + wn + cc;
                float s = stg[r * 32 + cc] * 0.125f;
                if (Mb[gi] == 1) s = -1e9f;
                Cf[gi] = s;
            }
        }
    }
}

// ---------------- fused fp32 -> fp16 converts ---------------------------------
__global__ __launch_bounds__(256) void f2h3(
    const float* __restrict__ x0, const float* __restrict__ x1,
    const float* __restrict__ x2, __half* __restrict__ y, int n4)
{   // y: 3 consecutive MT*DMODEL blocks
    const float* x = (blockIdx.y == 0) ? x0 : (blockIdx.y == 1) ? x1 : x2;
    __half* yo = y + (size_t)blockIdx.y * MT * DMODEL;
    int i = blockIdx.x * 256 + threadIdx.x;
    if (i < n4) {
        float4 v = ((const float4*)x)[i];
        __half2 a = __floats2half2_rn(v.x, v.y);
        __half2 b = __floats2half2_rn(v.z, v.w);
        uint2 u; u.x = *(uint32_t*)&a; u.y = *(uint32_t*)&b;
        ((uint2*)yo)[i] = u;
    }
}

__global__ __launch_bounds__(256) void f2h4(
    const float* __restrict__ x0, const float* __restrict__ x1,
    const float* __restrict__ x2, const float* __restrict__ x3,
    __half* __restrict__ y, int n4)   // y: 4 consecutive DMODEL^2 blocks
{
    const float* x = (blockIdx.y == 0) ? x0 : (blockIdx.y == 1) ? x1
                   : (blockIdx.y == 2) ? x2 : x3;
    __half* yo = y + (size_t)blockIdx.y * DMODEL * DMODEL;
    int i = blockIdx.x * 256 + threadIdx.x;
    if (i < n4) {
        float4 v = ((const float4*)x)[i];
        __half2 a = __floats2half2_rn(v.x, v.y);
        __half2 b = __floats2half2_rn(v.z, v.w);
        uint2 u; u.x = *(uint32_t*)&a; u.y = *(uint32_t*)&b;
        ((uint2*)yo)[i] = u;
    }
}

// ---------------- softmax over pre-masked scaled rows -> fp16 -----------------
__global__ __launch_bounds__(256) void softmax_rows(
    const float* __restrict__ S, __half* __restrict__ Ao)
{
    const long long row = blockIdx.x;
    const float* sr = S + row * (long long)SEQ;
    __half* ar = Ao + row * (long long)SEQ;
    const int t = threadIdx.x;

    float v[8];
    float mx = -3.0e38f;
#pragma unroll
    for (int i = 0; i < 8; i++) {
        v[i] = sr[t + i * 256];
        mx = fmaxf(mx, v[i]);
    }

    __shared__ float red[8];
#pragma unroll
    for (int o = 16; o; o >>= 1) mx = fmaxf(mx, __shfl_xor_sync(~0u, mx, o));
    if ((t & 31) == 0) red[t >> 5] = mx;
    __syncthreads();
    mx = red[0];
#pragma unroll
    for (int i = 1; i < 8; i++) mx = fmaxf(mx, red[i]);

    float sum = 0.f;
#pragma unroll
    for (int i = 0; i < 8; i++) {
        v[i] = exp2f((v[i] - mx) * 1.4426950408889634f);
        sum += v[i];
    }
#pragma unroll
    for (int o = 16; o; o >>= 1) sum += __shfl_xor_sync(~0u, sum, o);
    __syncthreads();
    if ((t & 31) == 0) red[t >> 5] = sum;
    __syncthreads();
    sum = 0.f;
#pragma unroll
    for (int i = 0; i < 8; i++) sum += red[i];
    float inv = 1.0f / sum;
#pragma unroll
    for (int i = 0; i < 8; i++) ar[t + i * 256] = __float2half_rn(v[i] * inv);
}

// ---------------- residual add + LayerNorm -----------------------------------
__global__ __launch_bounds__(256) void add_layernorm(
    const float* __restrict__ P, const float* __restrict__ R,
    const float* __restrict__ gamma, const float* __restrict__ beta,
    float* __restrict__ O)
{
    const long long row = blockIdx.x;
    const float* pr = P + row * (long long)DMODEL;
    const float* rr = R + row * (long long)DMODEL;
    float* orow = O + row * (long long)DMODEL;
    const int t = threadIdx.x;

    float x[4];
    float s = 0.f;
#pragma unroll
    for (int i = 0; i < 4; i++) {
        int c = t + i * 256;
        x[i] = pr[c] + rr[c];
        s += x[i];
    }

    __shared__ float red[8];
#pragma unroll
    for (int o = 16; o; o >>= 1) s += __shfl_xor_sync(~0u, s, o);
    if ((t & 31) == 0) red[t >> 5] = s;
    __syncthreads();
    s = 0.f;
#pragma unroll
    for (int i = 0; i < 8; i++) s += red[i];
    const float mu = s * (1.0f / DMODEL);

    float vq = 0.f;
#pragma unroll
    for (int i = 0; i < 4; i++) {
        float d = x[i] - mu;
        vq += d * d;
    }
#pragma unroll
    for (int o = 16; o; o >>= 1) vq += __shfl_xor_sync(~0u, vq, o);
    __syncthreads();
    if ((t & 31) == 0) red[t >> 5] = vq;
    __syncthreads();
    vq = 0.f;
#pragma unroll
    for (int i = 0; i < 8; i++) vq += red[i];
    const float rs = rsqrtf(vq * (1.0f / DMODEL) + 1e-5f);

#pragma unroll
    for (int i = 0; i < 4; i++) {
        int c = t + i * 256;
        orow[c] = (x[i] - mu) * rs * gamma[c] + beta[c];
    }
}

// ---------------- launch ------------------------------------------------------
extern "C" void kernel_launch(void* const* d_in, const int* in_sizes, int n_in,
                              void* d_out, int out_size)
{
    (void)in_sizes; (void)n_in; (void)out_size;
    const float* inQ  = (const float*)d_in[0];
    const float* inK  = (const float*)d_in[1];
    const float* inV  = (const float*)d_in[2];
    const int*   mask = (const int*)  d_in[3];
    const float* WQ   = (const float*)d_in[4];
    const float* WK   = (const float*)d_in[5];
    const float* WV   = (const float*)d_in[6];
    const float* WO   = (const float*)d_in[7];
    const float* gam  = (const float*)d_in[8];
    const float* bet  = (const float*)d_in[9];
    float* out = (float*)d_out;

    void *pIN, *pW4, *pQKV, *pA, *pWv, *pS, *pP;
    cudaGetSymbolAddress(&pIN,  g_hIN);
    cudaGetSymbolAddress(&pW4,  g_hW4);
    cudaGetSymbolAddress(&pQKV, g_hQKV);
    cudaGetSymbolAddress(&pA,   g_hA);
    cudaGetSymbolAddress(&pWv,  g_hWv);
    cudaGetSymbolAddress(&pS,   g_S);
    cudaGetSymbolAddress(&pP,   g_P);
    __half* hIN  = (__half*)pIN;                 // 3 blocks: inQ,inK,inV
    __half* hW   = (__half*)pW4;                 // 4 blocks: WQ,WK,WV,WO
    __half* hWO  = hW + 3 * (size_t)DMODEL * DMODEL;
    __half* hQKV = (__half*)pQKV;                // 3 blocks: Q,K,V
    __half* hQ   = hQKV;
    __half* hK   = hQKV + (size_t)MT * DMODEL;
    __half* hV   = hQKV + 2 * (size_t)MT * DMODEL;
    __half* hA   = (__half*)pA;
    __half* hWv  = (__half*)pWv;
    float*  S    = (float*)pS;
    float*  P    = (float*)pP;

    cudaFuncSetAttribute(gemm_h<true, 1>,
                         cudaFuncAttributeMaxDynamicSharedMemorySize, GSMEM);
    cudaFuncSetAttribute(gemm_h<true, 0>,
                         cudaFuncAttributeMaxDynamicSharedMemorySize, GSMEM);
    cudaFuncSetAttribute(gemm_h<true, 2>,
                         cudaFuncAttributeMaxDynamicSharedMemorySize, GSMEM);
    cudaFuncSetAttribute(gemm_h<false, 1>,
                         cudaFuncAttributeMaxDynamicSharedMemorySize, GSMEM);

    const dim3 blk(256);
    const long long sQK = (long long)SEQ * DMODEL;    // per-batch Q/K/V stride
    const long long sSS = (long long)SEQ * SEQ;       // per-batch scores stride
    const long long sIN = (long long)MT * DMODEL;     // per-matrix input stride
    const long long sW  = (long long)DMODEL * DMODEL; // per-matrix weight stride

    // launch 1-2: fused fp32 -> fp16 converts
    const int nBig4 = MT * DMODEL / 4;
    const int nW4   = DMODEL * DMODEL / 4;
    f2h3<<<dim3((nBig4 + 255) / 256, 3), 256>>>(inQ, inK, inV, hIN, nBig4);
    f2h4<<<dim3((nW4 + 255) / 256, 4), 256>>>(WQ, WK, WV, WO, hW, nW4);

    // launch 3: ALL THREE projections as one batched GEMM (z=0..2)
    gemm_h<true, 1><<<dim3(DMODEL / BN, MT / BM, 3), blk, GSMEM>>>(
        hIN, hW, hQKV, nullptr, DMODEL, DMODEL, sIN, sW, sIN);

    // launch 4: scores = Q*K^T with fused mask+scale -> fp32 (z=0..3 batches)
    gemm_h<true, 2><<<dim3(SEQ / BN, SEQ / BM, NB), blk, GSMEM>>>(
        hQ, hK, S, mask, SEQ, DMODEL, sQK, sQK, sSS);

    // launch 5: softmax over pre-masked rows -> fp16 attn
    softmax_rows<<<NB * SEQ, 256>>>(S, hA);

    // launch 6 (ncu target): attn @ V (NN) -> half
    gemm_h<false, 1><<<dim3(DMODEL / BN, SEQ / BM, NB), blk, GSMEM>>>(
        hA, hV, hWv, nullptr, DMODEL, SEQ, sSS, sQK, sQK);

    // launch 7: out proj -> fp32
    gemm_h<true, 0><<<dim3(DMODEL / BN, MT / BM, 1), blk, GSMEM>>>(
        hWv, hWO, P, nullptr, DMODEL, DMODEL, 0, 0, 0);

    // launch 8: residual + layernorm -> d_out
    add_layernorm<<<MT, 256>>>(P, inQ, gam, bet, out);
}

// round 10
// speedup vs baseline: 1.2132x; 1.0384x over previous
#include <cuda_runtime.h>
#include <cuda_fp16.h>
#include <cstdint>

// Problem constants (fixed shapes)
#define DMODEL 1024
#define SEQ    2048
#define NB     4
#define MT     (NB * SEQ)   // 8192 total rows

// ---------------- scratch (device globals; no allocation allowed) -----------
__device__ unsigned short g_hIN[3][(size_t)MT * DMODEL];     // inQ,inK,inV (half)
__device__ unsigned short g_hW4[4][(size_t)DMODEL * DMODEL]; // WQ,WK,WV,WO (half)
__device__ unsigned short g_hQKV[3][(size_t)MT * DMODEL];    // projQ,K,V (half)
__device__ unsigned short g_hVt[(size_t)MT * DMODEL];        // V^T per batch (half)
__device__ unsigned short g_hA[(size_t)NB * SEQ * SEQ];      // attn (half)
__device__ unsigned short g_hWv[(size_t)MT * DMODEL];        // attn@V (half)
__device__ float g_S[(size_t)NB * SEQ * SEQ];                // masked scaled scores
__device__ float g_P[(size_t)MT * DMODEL];                   // out proj (fp32)

// ---------------- PTX helpers -------------------------------------------------
__device__ __forceinline__ void cp16(uint32_t saddr, const void* gptr) {
    asm volatile("cp.async.cg.shared.global [%0], [%1], 16;\n"
                 :: "r"(saddr), "l"(gptr) : "memory");
}
__device__ __forceinline__ void cp_commit() {
    asm volatile("cp.async.commit_group;\n" ::: "memory");
}
__device__ __forceinline__ void ldsm4(uint32_t* r, uint32_t addr) {
    asm volatile("ldmatrix.sync.aligned.m8n8.x4.shared.b16 {%0,%1,%2,%3}, [%4];"
                 : "=r"(r[0]), "=r"(r[1]), "=r"(r[2]), "=r"(r[3]) : "r"(addr));
}
__device__ __forceinline__ void mma16816(float* d, const uint32_t* a,
                                         uint32_t b0, uint32_t b1) {
    asm volatile(
        "mma.sync.aligned.m16n8k16.row.col.f32.f16.f16.f32 "
        "{%0,%1,%2,%3}, {%4,%5,%6,%7}, {%8,%9}, {%0,%1,%2,%3};"
        : "+f"(d[0]), "+f"(d[1]), "+f"(d[2]), "+f"(d[3])
        : "r"(a[0]), "r"(a[1]), "r"(a[2]), "r"(a[3]), "r"(b0), "r"(b1));
}

// ---------------- fp16 NT GEMM: ldmatrix + mma.sync, SW128-swizzled smem -----
// C[M,N] = A[M,K] * B^T; A [M,K], B [N,K], both row-major K-major half.
// CTA tile 128x128, BK=64 (128B rows, conflict-free SW128), 8 warps 64x32,
// 3-stage cp.async, 2 CTAs/SM. Batched over blockIdx.z with strides.
// EPI: 0 = fp32 direct, 1 = fp16 staged, 2 = mask+scale fp32 direct (scores).
constexpr int BM = 128, BN = 128, BK = 64, STG = 3;
constexpr int TSZ = 128 * 128;                  // bytes per (A or B) tile stage
constexpr int GSMEM = STG * 2 * TSZ;            // 98304 B; 2 CTAs fit in 228KB

template <int EPI>
__global__ __launch_bounds__(256, 2) void gemm_h(
    const __half* __restrict__ A, const __half* __restrict__ Bm,
    void* __restrict__ Cv, const int* __restrict__ mask,
    int N, int K, long long sA, long long sB, long long sC)
{
    A  += (long long)blockIdx.z * sA;
    Bm += (long long)blockIdx.z * sB;

    extern __shared__ __half smh[];
    const uint32_t sbase = (uint32_t)__cvta_generic_to_shared(smh);

    const int t   = threadIdx.x;
    const int w   = t >> 5;
    const int ln  = t & 31;
    const int wm  = (w >> 2) * 64;   // 2 warps along M
    const int wn  = (w & 3) * 32;    // 4 warps along N
    const int bm  = blockIdx.y * BM;
    const int bn  = blockIdx.x * BN;

    // swizzled stage loader: tile = 128 rows x 128B, chunk c (16B) at
    // r*128 + ((c ^ (r&7))<<4). 1024 chunks per tile, 4 per thread.
    auto load_stage = [&](int s, int k0) {
        uint32_t ab = sbase + (uint32_t)(s * 2 * TSZ);
        uint32_t bb = ab + TSZ;
#pragma unroll
        for (int i = 0; i < 4; i++) {
            int idx = t + i * 256;
            int r = idx >> 3, c = idx & 7;
            uint32_t off = (uint32_t)(r * 128) + (uint32_t)(((c ^ (r & 7)) << 4));
            cp16(ab + off, &A[(long long)(bm + r) * K + k0 + c * 8]);
        }
#pragma unroll
        for (int i = 0; i < 4; i++) {
            int idx = t + i * 256;
            int r = idx >> 3, c = idx & 7;
            uint32_t off = (uint32_t)(r * 128) + (uint32_t)(((c ^ (r & 7)) << 4));
            cp16(bb + off, &Bm[(long long)(bn + r) * K + k0 + c * 8]);
        }
    };

    float acc[4][4][4];
#pragma unroll
    for (int i = 0; i < 4; i++)
#pragma unroll
        for (int j = 0; j < 4; j++)
#pragma unroll
            for (int e = 0; e < 4; e++) acc[i][j][e] = 0.0f;

    // lane-constant address pieces (ldmatrix x4: lanes 0-15 chunk c, 16-31 c+1)
    const int r16  = ln & 15;        // row within 16-row fragment
    const int cbit = ln >> 4;        // +1 chunk for upper half lanes
    const int x7   = ln & 7;         // (row & 7) for swizzle

    // one K=16 step: 4 A-frags (64 rows) + 2 B-x4 (32 n) -> 16 mma
    auto compute_ks = [&](uint32_t aSt, uint32_t bSt, int ks) {
        const uint32_t xr = (uint32_t)(((2 * ks + cbit) ^ x7) << 4);
        uint32_t a[4][4];
#pragma unroll
        for (int mi = 0; mi < 4; mi++)
            ldsm4(a[mi], aSt + (uint32_t)((wm + mi * 16 + r16) * 128) + xr);
        uint32_t bq[2][4];
#pragma unroll
        for (int nb = 0; nb < 2; nb++)
            ldsm4(bq[nb], bSt + (uint32_t)((wn + nb * 16 + r16) * 128) + xr);
#pragma unroll
        for (int mi = 0; mi < 4; mi++) {
            mma16816(acc[mi][0], a[mi], bq[0][0], bq[0][2]);
            mma16816(acc[mi][1], a[mi], bq[0][1], bq[0][3]);
            mma16816(acc[mi][2], a[mi], bq[1][0], bq[1][2]);
            mma16816(acc[mi][3], a[mi], bq[1][1], bq[1][3]);
        }
    };

    const int KT = K / BK;

#pragma unroll
    for (int s = 0; s < STG - 1; s++) { load_stage(s, s * BK); cp_commit(); }

    for (int kt = 0; kt < KT; kt++) {
        asm volatile("cp.async.wait_group 1;\n" ::: "memory");
        __syncthreads();

        const uint32_t aSt = sbase + (uint32_t)((kt % STG) * 2 * TSZ);
        const uint32_t bSt = aSt + TSZ;

        compute_ks(aSt, bSt, 0);           // tensor work first

        int f = kt + STG - 1;
        if (f < KT) load_stage(f % STG, f * BK);
        cp_commit();

        compute_ks(aSt, bSt, 1);
        compute_ks(aSt, bSt, 2);
        compute_ks(aSt, bSt, 3);
    }

    // acc frag element map: row = wm+mi*16+(ln>>2) (+8), col = wn+nj*8+(ln&3)*2
    const int fr = ln >> 2;
    const int fc = (ln & 3) * 2;

    if constexpr (EPI == 0) {
        float* Cf = (float*)Cv + (long long)blockIdx.z * sC;
#pragma unroll
        for (int mi = 0; mi < 4; mi++)
#pragma unroll
            for (int nj = 0; nj < 4; nj++) {
                long long row = bm + wm + mi * 16 + fr;
                long long col = bn + wn + nj * 8 + fc;
                float2 v0 = make_float2(acc[mi][nj][0], acc[mi][nj][1]);
                float2 v1 = make_float2(acc[mi][nj][2], acc[mi][nj][3]);
                *(float2*)&Cf[row * N + col]       = v0;
                *(float2*)&Cf[(row + 8) * N + col] = v1;
            }
    } else if constexpr (EPI == 2) {
        float* Cf = (float*)Cv + (long long)blockIdx.z * sC;
        const int* Mb = mask + (long long)blockIdx.z * sC;
#pragma unroll
        for (int mi = 0; mi < 4; mi++)
#pragma unroll
            for (int nj = 0; nj < 4; nj++) {
                long long row = bm + wm + mi * 16 + fr;
                long long col = bn + wn + nj * 8 + fc;
                long long g0 = row * N + col, g1 = (row + 8) * N + col;
                int2 m0 = *(const int2*)&Mb[g0];
                int2 m1 = *(const int2*)&Mb[g1];
                float2 v0, v1;
                v0.x = (m0.x == 1) ? -1e9f : acc[mi][nj][0] * 0.125f;
                v0.y = (m0.y == 1) ? -1e9f : acc[mi][nj][1] * 0.125f;
                v1.x = (m1.x == 1) ? -1e9f : acc[mi][nj][2] * 0.125f;
                v1.y = (m1.y == 1) ? -1e9f : acc[mi][nj][3] * 0.125f;
                *(float2*)&Cf[g0] = v0;
                *(float2*)&Cf[g1] = v1;
            }
    } else {
        // EPI == 1: stage fp32 accs in (reused) pipeline smem, 64x32 per warp
        __syncthreads();   // all warps done with LDSM reads of pipeline smem
        float* stg = (float*)smh + (size_t)w * 2048;
#pragma unroll
        for (int mi = 0; mi < 4; mi++)
#pragma unroll
            for (int nj = 0; nj < 4; nj++) {
                int r0 = mi * 16 + fr, c0 = nj * 8 + fc;
                stg[r0 * 32 + c0]           = acc[mi][nj][0];
                stg[r0 * 32 + c0 + 1]       = acc[mi][nj][1];
                stg[(r0 + 8) * 32 + c0]     = acc[mi][nj][2];
                stg[(r0 + 8) * 32 + c0 + 1] = acc[mi][nj][3];
            }
        __syncwarp();
        __half* Ch = (__half*)Cv + (long long)blockIdx.z * sC;
#pragma unroll
        for (int it = 0; it < 32; it++) {
            int g = it * 32 + ln;            // 1024 half2 chunks
            int r = g >> 4, cp = (g & 15) << 1;
            float2 v = *(const float2*)&stg[r * 32 + cp];
            __half2 h = __floats2half2_rn(v.x, v.y);
            *(__half2*)&Ch[(long long)(bm + wm + r) * N + bn + wn + cp] = h;
        }
    }
}

// ---------------- fused fp32 -> fp16 converts ---------------------------------
__global__ __launch_bounds__(256) void f2h3(
    const float* __restrict__ x0, const float* __restrict__ x1,
    const float* __restrict__ x2, __half* __restrict__ y, int n4)
{
    const float* x = (blockIdx.y == 0) ? x0 : (blockIdx.y == 1) ? x1 : x2;
    __half* yo = y + (size_t)blockIdx.y * MT * DMODEL;
    int i = blockIdx.x * 256 + threadIdx.x;
    if (i < n4) {
        float4 v = ((const float4*)x)[i];
        __half2 a = __floats2half2_rn(v.x, v.y);
        __half2 b = __floats2half2_rn(v.z, v.w);
        uint2 u; u.x = *(uint32_t*)&a; u.y = *(uint32_t*)&b;
        ((uint2*)yo)[i] = u;
    }
}

__global__ __launch_bounds__(256) void f2h4(
    const float* __restrict__ x0, const float* __restrict__ x1,
    const float* __restrict__ x2, const float* __restrict__ x3,
    __half* __restrict__ y, int n4)
{
    const float* x = (blockIdx.y == 0) ? x0 : (blockIdx.y == 1) ? x1
                   : (blockIdx.y == 2) ? x2 : x3;
    __half* yo = y + (size_t)blockIdx.y * DMODEL * DMODEL;
    int i = blockIdx.x * 256 + threadIdx.x;
    if (i < n4) {
        float4 v = ((const float4*)x)[i];
        __half2 a = __floats2half2_rn(v.x, v.y);
        __half2 b = __floats2half2_rn(v.z, v.w);
        uint2 u; u.x = *(uint32_t*)&a; u.y = *(uint32_t*)&b;
        ((uint2*)yo)[i] = u;
    }
}

// ---------------- fp16 V transpose (per batch): Vt[f][s] = V[s][f] ------------
__global__ __launch_bounds__(256) void transpose_h(
    const __half* __restrict__ V, __half* __restrict__ Vt)
{
    __shared__ __half tile[32][33];
    const __half* Vb = V  + (long long)blockIdx.z * SEQ * DMODEL;
    __half*      Vtb = Vt + (long long)blockIdx.z * DMODEL * SEQ;
    const int f0 = blockIdx.x * 32, s0 = blockIdx.y * 32;
    const int tx = threadIdx.x & 31, ty = (threadIdx.x >> 5) * 4;
#pragma unroll
    for (int i = 0; i < 4; i++)
        tile[ty + i][tx] = Vb[(long long)(s0 + ty + i) * DMODEL + f0 + tx];
    __syncthreads();
#pragma unroll
    for (int i = 0; i < 4; i++)
        Vtb[(long long)(f0 + ty + i) * SEQ + s0 + tx] = tile[tx][ty + i];
}

// ---------------- softmax over pre-masked scaled rows -> fp16 -----------------
__global__ __launch_bounds__(256) void softmax_rows(
    const float* __restrict__ S, __half* __restrict__ Ao)
{
    const long long row = blockIdx.x;
    const float* sr = S + row * (long long)SEQ;
    __half* ar = Ao + row * (long long)SEQ;
    const int t = threadIdx.x;

    float v[8];
    float mx = -3.0e38f;
#pragma unroll
    for (int i = 0; i < 8; i++) {
        v[i] = sr[t + i * 256];
        mx = fmaxf(mx, v[i]);
    }

    __shared__ float red[8];
#pragma unroll
    for (int o = 16; o; o >>= 1) mx = fmaxf(mx, __shfl_xor_sync(~0u, mx, o));
    if ((t & 31) == 0) red[t >> 5] = mx;
    __syncthreads();
    mx = red[0];
#pragma unroll
    for (int i = 1; i < 8; i++) mx = fmaxf(mx, red[i]);

    float sum = 0.f;
#pragma unroll
    for (int i = 0; i < 8; i++) {
        v[i] = exp2f((v[i] - mx) * 1.4426950408889634f);
        sum += v[i];
    }
#pragma unroll
    for (int o = 16; o; o >>= 1) sum += __shfl_xor_sync(~0u, sum, o);
    __syncthreads();
    if ((t & 31) == 0) red[t >> 5] = sum;
    __syncthreads();
    sum = 0.f;
#pragma unroll
    for (int i = 0; i < 8; i++) sum += red[i];
    float inv = 1.0f / sum;
#pragma unroll
    for (int i = 0; i < 8; i++) ar[t + i * 256] = __float2half_rn(v[i] * inv);
}

// ---------------- residual add + LayerNorm -----------------------------------
__global__ __launch_bounds__(256) void add_layernorm(
    const float* __restrict__ P, const float* __restrict__ R,
    const float* __restrict__ gamma, const float* __restrict__ beta,
    float* __restrict__ O)
{
    const long long row = blockIdx.x;
    const float* pr = P + row * (long long)DMODEL;
    const float* rr = R + row * (long long)DMODEL;
    float* orow = O + row * (long long)DMODEL;
    const int t = threadIdx.x;

    float x[4];
    float s = 0.f;
#pragma unroll
    for (int i = 0; i < 4; i++) {
        int c = t + i * 256;
        x[i] = pr[c] + rr[c];
        s += x[i];
    }

    __shared__ float red[8];
#pragma unroll
    for (int o = 16; o; o >>= 1) s += __shfl_xor_sync(~0u, s, o);
    if ((t & 31) == 0) red[t >> 5] = s;
    __syncthreads();
    s = 0.f;
#pragma unroll
    for (int i = 0; i < 8; i++) s += red[i];
    const float mu = s * (1.0f / DMODEL);

    float vq = 0.f;
#pragma unroll
    for (int i = 0; i < 4; i++) {
        float d = x[i] - mu;
        vq += d * d;
    }
#pragma unroll
    for (int o = 16; o; o >>= 1) vq += __shfl_xor_sync(~0u, vq, o);
    __syncthreads();
    if ((t & 31) == 0) red[t >> 5] = vq;
    __syncthreads();
    vq = 0.f;
#pragma unroll
    for (int i = 0; i < 8; i++) vq += red[i];
    const float rs = rsqrtf(vq * (1.0f / DMODEL) + 1e-5f);

#pragma unroll
    for (int i = 0; i < 4; i++) {
        int c = t + i * 256;
        orow[c] = (x[i] - mu) * rs * gamma[c] + beta[c];
    }
}

// ---------------- launch ------------------------------------------------------
extern "C" void kernel_launch(void* const* d_in, const int* in_sizes, int n_in,
                              void* d_out, int out_size)
{
    (void)in_sizes; (void)n_in; (void)out_size;
    const float* inQ  = (const float*)d_in[0];
    const float* inK  = (const float*)d_in[1];
    const float* inV  = (const float*)d_in[2];
    const int*   mask = (const int*)  d_in[3];
    const float* WQ   = (const float*)d_in[4];
    const float* WK   = (const float*)d_in[5];
    const float* WV   = (const float*)d_in[6];
    const float* WO   = (const float*)d_in[7];
    const float* gam  = (const float*)d_in[8];
    const float* bet  = (const float*)d_in[9];
    float* out = (float*)d_out;

    void *pIN, *pW4, *pQKV, *pVt, *pA, *pWv, *pS, *pP;
    cudaGetSymbolAddress(&pIN,  g_hIN);
    cudaGetSymbolAddress(&pW4,  g_hW4);
    cudaGetSymbolAddress(&pQKV, g_hQKV);
    cudaGetSymbolAddress(&pVt,  g_hVt);
    cudaGetSymbolAddress(&pA,   g_hA);
    cudaGetSymbolAddress(&pWv,  g_hWv);
    cudaGetSymbolAddress(&pS,   g_S);
    cudaGetSymbolAddress(&pP,   g_P);
    __half* hIN  = (__half*)pIN;
    __half* hW   = (__half*)pW4;
    __half* hWO  = hW + 3 * (size_t)DMODEL * DMODEL;
    __half* hQKV = (__half*)pQKV;
    __half* hQ   = hQKV;
    __half* hK   = hQKV + (size_t)MT * DMODEL;
    __half* hV   = hQKV + 2 * (size_t)MT * DMODEL;
    __half* hVt  = (__half*)pVt;
    __half* hA   = (__half*)pA;
    __half* hWv  = (__half*)pWv;
    float*  S    = (float*)pS;
    float*  P    = (float*)pP;

    cudaFuncSetAttribute(gemm_h<0>,
                         cudaFuncAttributeMaxDynamicSharedMemorySize, GSMEM);
    cudaFuncSetAttribute(gemm_h<1>,
                         cudaFuncAttributeMaxDynamicSharedMemorySize, GSMEM);
    cudaFuncSetAttribute(gemm_h<2>,
                         cudaFuncAttributeMaxDynamicSharedMemorySize, GSMEM);

    const dim3 blk(256);
    const long long sQK = (long long)SEQ * DMODEL;    // per-batch Q/K/V stride
    const long long sSS = (long long)SEQ * SEQ;       // per-batch scores stride
    const long long sVT = (long long)DMODEL * SEQ;    // per-batch V^T stride
    const long long sIN = (long long)MT * DMODEL;     // per-matrix input stride
    const long long sW  = (long long)DMODEL * DMODEL; // per-matrix weight stride

    // fused fp32 -> fp16 converts
    const int nBig4 = MT * DMODEL / 4;
    const int nW4   = DMODEL * DMODEL / 4;
    f2h3<<<dim3((nBig4 + 255) / 256, 3), 256>>>(inQ, inK, inV, hIN, nBig4);
    f2h4<<<dim3((nW4 + 255) / 256, 4), 256>>>(WQ, WK, WV, WO, hW, nW4);

    // ALL THREE projections as one batched NT GEMM (z=0..2)
    gemm_h<1><<<dim3(DMODEL / BN, MT / BM, 3), blk, GSMEM>>>(
        hIN, hW, hQKV, nullptr, DMODEL, DMODEL, sIN, sW, sIN);

    // V^T per batch (for NT PV GEMM)
    transpose_h<<<dim3(DMODEL / 32, SEQ / 32, NB), 256>>>(hV, hVt);

    // scores = Q*K^T with fused mask+scale -> fp32 (NT, z=0..3)
    gemm_h<2><<<dim3(SEQ / BN, SEQ / BM, NB), blk, GSMEM>>>(
        hQ, hK, S, mask, SEQ, DMODEL, sQK, sQK, sSS);

    // softmax over pre-masked rows -> fp16 attn
    softmax_rows<<<NB * SEQ, 256>>>(S, hA);

    // attn @ V = A * (V^T)^T (NT with B = V^T) -> half
    gemm_h<1><<<dim3(DMODEL / BN, SEQ / BM, NB), blk, GSMEM>>>(
        hA, hVt, hWv, nullptr, DMODEL, SEQ, sSS, sVT, sQK);

    // out proj: W * WO^T (NT) -> fp32
    gemm_h<0><<<dim3(DMODEL / BN, MT / BM, 1), blk, GSMEM>>>(
        hWv, hWO, P, nullptr, DMODEL, DMODEL, 0, 0, 0);

    // residual + layernorm -> d_out
    add_layernorm<<<MT, 256>>>(P, inQ, gam, bet, out);
}

// round 11
// speedup vs baseline: 1.2389x; 1.0211x over previous
#include <cuda_runtime.h>
#include <cuda_fp16.h>
#include <cstdint>

// Problem constants (fixed shapes)
#define DMODEL 1024
#define SEQ    2048
#define NB     4
#define MT     (NB * SEQ)   // 8192 total rows

// ---------------- scratch (device globals; no allocation allowed) -----------
__device__ unsigned short g_hIN[3][(size_t)MT * DMODEL];     // inQ,inK,inV (half)
__device__ unsigned short g_hW4[4][(size_t)DMODEL * DMODEL]; // WQ,WK,WV,WO (half)
__device__ unsigned short g_hQKV[3][(size_t)MT * DMODEL];    // projQ,K (V slot unused)
__device__ unsigned short g_hVt[(size_t)MT * DMODEL];        // V^T per batch (half)
__device__ unsigned short g_hA[(size_t)NB * SEQ * SEQ];      // attn (half)
__device__ unsigned short g_hWv[(size_t)MT * DMODEL];        // attn@V (half)
__device__ float g_S[(size_t)NB * SEQ * SEQ];                // masked scaled scores
__device__ float g_P[(size_t)MT * DMODEL];                   // out proj (fp32)

// ---------------- PTX helpers -------------------------------------------------
__device__ __forceinline__ void cp16(uint32_t saddr, const void* gptr) {
    asm volatile("cp.async.cg.shared.global [%0], [%1], 16;\n"
                 :: "r"(saddr), "l"(gptr) : "memory");
}
__device__ __forceinline__ void cp_commit() {
    asm volatile("cp.async.commit_group;\n" ::: "memory");
}
__device__ __forceinline__ void ldsm4(uint32_t* r, uint32_t addr) {
    asm volatile("ldmatrix.sync.aligned.m8n8.x4.shared.b16 {%0,%1,%2,%3}, [%4];"
                 : "=r"(r[0]), "=r"(r[1]), "=r"(r[2]), "=r"(r[3]) : "r"(addr));
}
__device__ __forceinline__ void mma16816(float* d, const uint32_t* a,
                                         uint32_t b0, uint32_t b1) {
    asm volatile(
        "mma.sync.aligned.m16n8k16.row.col.f32.f16.f16.f32 "
        "{%0,%1,%2,%3}, {%4,%5,%6,%7}, {%8,%9}, {%0,%1,%2,%3};"
        : "+f"(d[0]), "+f"(d[1]), "+f"(d[2]), "+f"(d[3])
        : "r"(a[0]), "r"(a[1]), "r"(a[2]), "r"(a[3]), "r"(b0), "r"(b1));
}

// ---------------- fp16 NT GEMM: ldmatrix + mma.sync, SW128-swizzled smem -----
// C[M,N] = A[M,K] * B^T; A [M,K], B [N,K], both row-major K-major half.
// CTA tile 128x128, BK=64 (128B rows, conflict-free SW128), 8 warps 64x32,
// 3-stage cp.async, 2 CTAs/SM. Batched over blockIdx.z with strides.
// EPI: 0 = fp32 direct, 1 = fp16 staged (+ optional V^T side-write for z==2),
//      2 = mask+scale fp32 direct (scores epilogue).
constexpr int BM = 128, BN = 128, BK = 64, STG = 3;
constexpr int TSZ = 128 * 128;                  // bytes per (A or B) tile stage
constexpr int GSMEM = STG * 2 * TSZ;            // 98304 B; 2 CTAs fit in 228KB
constexpr int SP = 33;                          // fp32 staging stride (pad)

template <int EPI>
__global__ __launch_bounds__(256, 2) void gemm_h(
    const __half* __restrict__ A, const __half* __restrict__ Bm,
    void* __restrict__ Cv, const int* __restrict__ mask,
    __half* __restrict__ vt,
    int N, int K, long long sA, long long sB, long long sC)
{
    A  += (long long)blockIdx.z * sA;
    Bm += (long long)blockIdx.z * sB;

    extern __shared__ __half smh[];
    const uint32_t sbase = (uint32_t)__cvta_generic_to_shared(smh);

    const int t   = threadIdx.x;
    const int w   = t >> 5;
    const int ln  = t & 31;
    const int wm  = (w >> 2) * 64;   // 2 warps along M
    const int wn  = (w & 3) * 32;    // 4 warps along N
    const int bm  = blockIdx.y * BM;
    const int bn  = blockIdx.x * BN;

    // swizzled stage loader: tile = 128 rows x 128B, chunk c (16B) at
    // r*128 + ((c ^ (r&7))<<4). 1024 chunks per tile, 4 per thread.
    auto load_stage = [&](int s, int k0) {
        uint32_t ab = sbase + (uint32_t)(s * 2 * TSZ);
        uint32_t bb = ab + TSZ;
#pragma unroll
        for (int i = 0; i < 4; i++) {
            int idx = t + i * 256;
            int r = idx >> 3, c = idx & 7;
            uint32_t off = (uint32_t)(r * 128) + (uint32_t)(((c ^ (r & 7)) << 4));
            cp16(ab + off, &A[(long long)(bm + r) * K + k0 + c * 8]);
        }
#pragma unroll
        for (int i = 0; i < 4; i++) {
            int idx = t + i * 256;
            int r = idx >> 3, c = idx & 7;
            uint32_t off = (uint32_t)(r * 128) + (uint32_t)(((c ^ (r & 7)) << 4));
            cp16(bb + off, &Bm[(long long)(bn + r) * K + k0 + c * 8]);
        }
    };

    float acc[4][4][4];
#pragma unroll
    for (int i = 0; i < 4; i++)
#pragma unroll
        for (int j = 0; j < 4; j++)
#pragma unroll
            for (int e = 0; e < 4; e++) acc[i][j][e] = 0.0f;

    const int r16  = ln & 15;
    const int cbit = ln >> 4;
    const int x7   = ln & 7;

    auto compute_ks = [&](uint32_t aSt, uint32_t bSt, int ks) {
        const uint32_t xr = (uint32_t)(((2 * ks + cbit) ^ x7) << 4);
        uint32_t a[4][4];
#pragma unroll
        for (int mi = 0; mi < 4; mi++)
            ldsm4(a[mi], aSt + (uint32_t)((wm + mi * 16 + r16) * 128) + xr);
        uint32_t bq[2][4];
#pragma unroll
        for (int nb = 0; nb < 2; nb++)
            ldsm4(bq[nb], bSt + (uint32_t)((wn + nb * 16 + r16) * 128) + xr);
#pragma unroll
        for (int mi = 0; mi < 4; mi++) {
            mma16816(acc[mi][0], a[mi], bq[0][0], bq[0][2]);
            mma16816(acc[mi][1], a[mi], bq[0][1], bq[0][3]);
            mma16816(acc[mi][2], a[mi], bq[1][0], bq[1][2]);
            mma16816(acc[mi][3], a[mi], bq[1][1], bq[1][3]);
        }
    };

    const int KT = K / BK;

#pragma unroll
    for (int s = 0; s < STG - 1; s++) { load_stage(s, s * BK); cp_commit(); }

    for (int kt = 0; kt < KT; kt++) {
        asm volatile("cp.async.wait_group 1;\n" ::: "memory");
        __syncthreads();

        const uint32_t aSt = sbase + (uint32_t)((kt % STG) * 2 * TSZ);
        const uint32_t bSt = aSt + TSZ;

        compute_ks(aSt, bSt, 0);           // tensor work first

        int f = kt + STG - 1;
        if (f < KT) load_stage(f % STG, f * BK);
        cp_commit();

        compute_ks(aSt, bSt, 1);
        compute_ks(aSt, bSt, 2);
        compute_ks(aSt, bSt, 3);
    }

    const int fr = ln >> 2;
    const int fc = (ln & 3) * 2;

    if constexpr (EPI == 0) {
        float* Cf = (float*)Cv + (long long)blockIdx.z * sC;
#pragma unroll
        for (int mi = 0; mi < 4; mi++)
#pragma unroll
            for (int nj = 0; nj < 4; nj++) {
                long long row = bm + wm + mi * 16 + fr;
                long long col = bn + wn + nj * 8 + fc;
                float2 v0 = make_float2(acc[mi][nj][0], acc[mi][nj][1]);
                float2 v1 = make_float2(acc[mi][nj][2], acc[mi][nj][3]);
                *(float2*)&Cf[row * N + col]       = v0;
                *(float2*)&Cf[(row + 8) * N + col] = v1;
            }
    } else if constexpr (EPI == 2) {
        float* Cf = (float*)Cv + (long long)blockIdx.z * sC;
        const int* Mb = mask + (long long)blockIdx.z * sC;
#pragma unroll
        for (int mi = 0; mi < 4; mi++)
#pragma unroll
            for (int nj = 0; nj < 4; nj++) {
                long long row = bm + wm + mi * 16 + fr;
                long long col = bn + wn + nj * 8 + fc;
                long long g0 = row * N + col, g1 = (row + 8) * N + col;
                int2 m0 = *(const int2*)&Mb[g0];
                int2 m1 = *(const int2*)&Mb[g1];
                float2 v0, v1;
                v0.x = (m0.x == 1) ? -1e9f : acc[mi][nj][0] * 0.125f;
                v0.y = (m0.y == 1) ? -1e9f : acc[mi][nj][1] * 0.125f;
                v1.x = (m1.x == 1) ? -1e9f : acc[mi][nj][2] * 0.125f;
                v1.y = (m1.y == 1) ? -1e9f : acc[mi][nj][3] * 0.125f;
                *(float2*)&Cf[g0] = v0;
                *(float2*)&Cf[g1] = v1;
            }
    } else {
        // EPI == 1: stage fp32 accs in (reused) pipeline smem, 64x(32+pad)/warp
        __syncthreads();   // all warps done with LDSM reads of pipeline smem
        float* stg = (float*)smh + (size_t)w * (64 * SP);
#pragma unroll
        for (int mi = 0; mi < 4; mi++)
#pragma unroll
            for (int nj = 0; nj < 4; nj++) {
                int r0 = mi * 16 + fr, c0 = nj * 8 + fc;
                stg[r0 * SP + c0]           = acc[mi][nj][0];
                stg[r0 * SP + c0 + 1]       = acc[mi][nj][1];
                stg[(r0 + 8) * SP + c0]     = acc[mi][nj][2];
                stg[(r0 + 8) * SP + c0 + 1] = acc[mi][nj][3];
            }
        __syncwarp();
        if (vt != nullptr && blockIdx.z == 2) {
            // V^T side-write: Vt[batch][f][s] = V[s][f], coalesced half2 on s
            const int batch = bm / SEQ;
            const int sloc  = (bm % SEQ) + wm + 2 * ln;
            __half* Vtb = vt + (size_t)batch * DMODEL * SEQ;
#pragma unroll
            for (int c = 0; c < 32; c++) {
                float v0 = stg[(2 * ln) * SP + c];
                float v1 = stg[(2 * ln + 1) * SP + c];
                __half2 h = __floats2half2_rn(v0, v1);
                *(__half2*)&Vtb[(long long)(bn + wn + c) * SEQ + sloc] = h;
            }
        } else {
            __half* Ch = (__half*)Cv + (long long)blockIdx.z * sC;
#pragma unroll
            for (int it = 0; it < 32; it++) {
                int g = it * 32 + ln;            // 1024 half2 chunks
                int r = g >> 4, cp = (g & 15) << 1;
                float va = stg[r * SP + cp];
                float vb = stg[r * SP + cp + 1];
                __half2 h = __floats2half2_rn(va, vb);
                *(__half2*)&Ch[(long long)(bm + wm + r) * N + bn + wn + cp] = h;
            }
        }
    }
}

// ---------------- fused fp32 -> fp16 converts ---------------------------------
__global__ __launch_bounds__(256) void f2h3(
    const float* __restrict__ x0, const float* __restrict__ x1,
    const float* __restrict__ x2, __half* __restrict__ y, int n4)
{
    const float* x = (blockIdx.y == 0) ? x0 : (blockIdx.y == 1) ? x1 : x2;
    __half* yo = y + (size_t)blockIdx.y * MT * DMODEL;
    int i = blockIdx.x * 256 + threadIdx.x;
    if (i < n4) {
        float4 v = ((const float4*)x)[i];
        __half2 a = __floats2half2_rn(v.x, v.y);
        __half2 b = __floats2half2_rn(v.z, v.w);
        uint2 u; u.x = *(uint32_t*)&a; u.y = *(uint32_t*)&b;
        ((uint2*)yo)[i] = u;
    }
}

__global__ __launch_bounds__(256) void f2h4(
    const float* __restrict__ x0, const float* __restrict__ x1,
    const float* __restrict__ x2, const float* __restrict__ x3,
    __half* __restrict__ y, int n4)
{
    const float* x = (blockIdx.y == 0) ? x0 : (blockIdx.y == 1) ? x1
                   : (blockIdx.y == 2) ? x2 : x3;
    __half* yo = y + (size_t)blockIdx.y * DMODEL * DMODEL;
    int i = blockIdx.x * 256 + threadIdx.x;
    if (i < n4) {
        float4 v = ((const float4*)x)[i];
        __half2 a = __floats2half2_rn(v.x, v.y);
        __half2 b = __floats2half2_rn(v.z, v.w);
        uint2 u; u.x = *(uint32_t*)&a; u.y = *(uint32_t*)&b;
        ((uint2*)yo)[i] = u;
    }
}

// ---------------- softmax over pre-masked scaled rows -> fp16 (vectorized) ----
__global__ __launch_bounds__(256) void softmax_rows(
    const float* __restrict__ S, __half* __restrict__ Ao)
{
    const long long row = blockIdx.x;
    const float4* sr4 = (const float4*)(S + row * (long long)SEQ);
    uint2* ar2 = (uint2*)(Ao + row * (long long)SEQ);
    const int t = threadIdx.x;

    float4 q0 = sr4[t];
    float4 q1 = sr4[t + 256];
    float v[8] = {q0.x, q0.y, q0.z, q0.w, q1.x, q1.y, q1.z, q1.w};

    float mx = -3.0e38f;
#pragma unroll
    for (int i = 0; i < 8; i++) mx = fmaxf(mx, v[i]);

    __shared__ float red[8];
#pragma unroll
    for (int o = 16; o; o >>= 1) mx = fmaxf(mx, __shfl_xor_sync(~0u, mx, o));
    if ((t & 31) == 0) red[t >> 5] = mx;
    __syncthreads();
    mx = red[0];
#pragma unroll
    for (int i = 1; i < 8; i++) mx = fmaxf(mx, red[i]);

    float sum = 0.f;
#pragma unroll
    for (int i = 0; i < 8; i++) {
        v[i] = exp2f((v[i] - mx) * 1.4426950408889634f);
        sum += v[i];
    }
#pragma unroll
    for (int o = 16; o; o >>= 1) sum += __shfl_xor_sync(~0u, sum, o);
    __syncthreads();
    if ((t & 31) == 0) red[t >> 5] = sum;
    __syncthreads();
    sum = 0.f;
#pragma unroll
    for (int i = 0; i < 8; i++) sum += red[i];
    const float inv = 1.0f / sum;

    __half2 h0 = __floats2half2_rn(v[0] * inv, v[1] * inv);
    __half2 h1 = __floats2half2_rn(v[2] * inv, v[3] * inv);
    __half2 h2 = __floats2half2_rn(v[4] * inv, v[5] * inv);
    __half2 h3 = __floats2half2_rn(v[6] * inv, v[7] * inv);
    uint2 u0, u1;
    u0.x = *(uint32_t*)&h0; u0.y = *(uint32_t*)&h1;
    u1.x = *(uint32_t*)&h2; u1.y = *(uint32_t*)&h3;
    ar2[t]       = u0;
    ar2[t + 256] = u1;
}

// ---------------- residual add + LayerNorm (float4 single pass) ---------------
__global__ __launch_bounds__(256) void add_layernorm(
    const float* __restrict__ P, const float* __restrict__ R,
    const float* __restrict__ gamma, const float* __restrict__ beta,
    float* __restrict__ O)
{
    const long long row = blockIdx.x;
    const float4* pr4 = (const float4*)(P + row * (long long)DMODEL);
    const float4* rr4 = (const float4*)(R + row * (long long)DMODEL);
    float4* o4 = (float4*)(O + row * (long long)DMODEL);
    const int t = threadIdx.x;

    float4 p = pr4[t], r = rr4[t];
    float x[4] = {p.x + r.x, p.y + r.y, p.z + r.z, p.w + r.w};
    float s = x[0] + x[1] + x[2] + x[3];

    __shared__ float red[8];
#pragma unroll
    for (int o = 16; o; o >>= 1) s += __shfl_xor_sync(~0u, s, o);
    if ((t & 31) == 0) red[t >> 5] = s;
    __syncthreads();
    s = 0.f;
#pragma unroll
    for (int i = 0; i < 8; i++) s += red[i];
    const float mu = s * (1.0f / DMODEL);

    float vq = 0.f;
#pragma unroll
    for (int i = 0; i < 4; i++) {
        float d = x[i] - mu;
        vq += d * d;
    }
#pragma unroll
    for (int o = 16; o; o >>= 1) vq += __shfl_xor_sync(~0u, vq, o);
    __syncthreads();
    if ((t & 31) == 0) red[t >> 5] = vq;
    __syncthreads();
    vq = 0.f;
#pragma unroll
    for (int i = 0; i < 8; i++) vq += red[i];
    const float rs = rsqrtf(vq * (1.0f / DMODEL) + 1e-5f);

    float4 g = ((const float4*)gamma)[t];
    float4 b = ((const float4*)beta)[t];
    float4 o;
    o.x = (x[0] - mu) * rs * g.x + b.x;
    o.y = (x[1] - mu) * rs * g.y + b.y;
    o.z = (x[2] - mu) * rs * g.z + b.z;
    o.w = (x[3] - mu) * rs * g.w + b.w;
    o4[t] = o;
}

// ---------------- launch ------------------------------------------------------
extern "C" void kernel_launch(void* const* d_in, const int* in_sizes, int n_in,
                              void* d_out, int out_size)
{
    (void)in_sizes; (void)n_in; (void)out_size;
    const float* inQ  = (const float*)d_in[0];
    const float* inK  = (const float*)d_in[1];
    const float* inV  = (const float*)d_in[2];
    const int*   mask = (const int*)  d_in[3];
    const float* WQ   = (const float*)d_in[4];
    const float* WK   = (const float*)d_in[5];
    const float* WV   = (const float*)d_in[6];
    const float* WO   = (const float*)d_in[7];
    const float* gam  = (const float*)d_in[8];
    const float* bet  = (const float*)d_in[9];
    float* out = (float*)d_out;

    void *pIN, *pW4, *pQKV, *pVt, *pA, *pWv, *pS, *pP;
    cudaGetSymbolAddress(&pIN,  g_hIN);
    cudaGetSymbolAddress(&pW4,  g_hW4);
    cudaGetSymbolAddress(&pQKV, g_hQKV);
    cudaGetSymbolAddress(&pVt,  g_hVt);
    cudaGetSymbolAddress(&pA,   g_hA);
    cudaGetSymbolAddress(&pWv,  g_hWv);
    cudaGetSymbolAddress(&pS,   g_S);
    cudaGetSymbolAddress(&pP,   g_P);
    __half* hIN  = (__half*)pIN;
    __half* hW   = (__half*)pW4;
    __half* hWO  = hW + 3 * (size_t)DMODEL * DMODEL;
    __half* hQKV = (__half*)pQKV;
    __half* hQ   = hQKV;
    __half* hK   = hQKV + (size_t)MT * DMODEL;
    __half* hVt  = (__half*)pVt;
    __half* hA   = (__half*)pA;
    __half* hWv  = (__half*)pWv;
    float*  S    = (float*)pS;
    float*  P    = (float*)pP;

    cudaFuncSetAttribute(gemm_h<0>,
                         cudaFuncAttributeMaxDynamicSharedMemorySize, GSMEM);
    cudaFuncSetAttribute(gemm_h<1>,
                         cudaFuncAttributeMaxDynamicSharedMemorySize, GSMEM);
    cudaFuncSetAttribute(gemm_h<2>,
                         cudaFuncAttributeMaxDynamicSharedMemorySize, GSMEM);

    const dim3 blk(256);
    const long long sQK = (long long)SEQ * DMODEL;    // per-batch Q/K stride
    const long long sSS = (long long)SEQ * SEQ;       // per-batch scores stride
    const long long sVT = (long long)DMODEL * SEQ;    // per-batch V^T stride
    const long long sIN = (long long)MT * DMODEL;     // per-matrix input stride
    const long long sW  = (long long)DMODEL * DMODEL; // per-matrix weight stride

    // launch 1-2: fused fp32 -> fp16 converts
    const int nBig4 = MT * DMODEL / 4;
    const int nW4   = DMODEL * DMODEL / 4;
    f2h3<<<dim3((nBig4 + 255) / 256, 3), 256>>>(inQ, inK, inV, hIN, nBig4);
    f2h4<<<dim3((nW4 + 255) / 256, 4), 256>>>(WQ, WK, WV, WO, hW, nW4);

    // launch 3: batched Q/K/V projections (z=0..2); z==2 writes V^T directly
    gemm_h<1><<<dim3(DMODEL / BN, MT / BM, 3), blk, GSMEM>>>(
        hIN, hW, hQKV, nullptr, hVt, DMODEL, DMODEL, sIN, sW, sIN);

    // launch 4 (ncu slot): scores = Q*K^T with fused mask+scale -> fp32
    gemm_h<2><<<dim3(SEQ / BN, SEQ / BM, NB), blk, GSMEM>>>(
        hQ, hK, S, mask, nullptr, SEQ, DMODEL, sQK, sQK, sSS);

    // launch 5: softmax over pre-masked rows -> fp16 attn
    softmax_rows<<<NB * SEQ, 256>>>(S, hA);

    // launch 6: attn @ V = A * (V^T)^T (NT with B = V^T) -> half
    gemm_h<1><<<dim3(DMODEL / BN, SEQ / BM, NB), blk, GSMEM>>>(
        hA, hVt, hWv, nullptr, nullptr, DMODEL, SEQ, sSS, sVT, sQK);

    // launch 7: out proj: W * WO^T (NT) -> fp32
    gemm_h<0><<<dim3(DMODEL / BN, MT / BM, 1), blk, GSMEM>>>(
        hWv, hWO, P, nullptr, nullptr, DMODEL, DMODEL, 0, 0, 0);

    // launch 8: residual + layernorm -> d_out
    add_layernorm<<<MT, 256>>>(P, inQ, gam, bet, out);
}

// round 12
// speedup vs baseline: 1.2779x; 1.0315x over previous
#include <cuda_runtime.h>
#include <cuda_fp16.h>
#include <cstdint>

// Problem constants (fixed shapes)
#define DMODEL 1024
#define SEQ    2048
#define NB     4
#define MT     (NB * SEQ)   // 8192 total rows

// ---------------- scratch (device globals; no allocation allowed) -----------
__device__ unsigned short g_hIN[3][(size_t)MT * DMODEL];     // inQ,inK,inV (half)
__device__ unsigned short g_hW4[4][(size_t)DMODEL * DMODEL]; // WQ,WK,WV,WO (half)
__device__ unsigned short g_hQKV[3][(size_t)MT * DMODEL];    // projQ,K (V slot unused)
__device__ unsigned short g_hVt[(size_t)MT * DMODEL];        // V^T per batch (half)
__device__ unsigned short g_hA[(size_t)NB * SEQ * SEQ];      // attn (half)
__device__ unsigned short g_hWv[(size_t)MT * DMODEL];        // attn@V (half)
__device__ float g_S[(size_t)NB * SEQ * SEQ];                // masked scaled scores
__device__ float g_P[(size_t)MT * DMODEL];                   // out proj (fp32)

// ---------------- PTX helpers -------------------------------------------------
__device__ __forceinline__ void cp16(uint32_t saddr, const void* gptr) {
    asm volatile("cp.async.cg.shared.global [%0], [%1], 16;\n"
                 :: "r"(saddr), "l"(gptr) : "memory");
}
__device__ __forceinline__ void cp_commit() {
    asm volatile("cp.async.commit_group;\n" ::: "memory");
}
__device__ __forceinline__ void ldsm4(uint32_t* r, uint32_t addr) {
    asm volatile("ldmatrix.sync.aligned.m8n8.x4.shared.b16 {%0,%1,%2,%3}, [%4];"
                 : "=r"(r[0]), "=r"(r[1]), "=r"(r[2]), "=r"(r[3]) : "r"(addr));
}
__device__ __forceinline__ void mma16816(float* d, const uint32_t* a,
                                         uint32_t b0, uint32_t b1) {
    asm volatile(
        "mma.sync.aligned.m16n8k16.row.col.f32.f16.f16.f32 "
        "{%0,%1,%2,%3}, {%4,%5,%6,%7}, {%8,%9}, {%0,%1,%2,%3};"
        : "+f"(d[0]), "+f"(d[1]), "+f"(d[2]), "+f"(d[3])
        : "r"(a[0]), "r"(a[1]), "r"(a[2]), "r"(a[3]), "r"(b0), "r"(b1));
}

// ---------------- fp16 NT GEMM: ldmatrix + mma.sync, SW128-swizzled smem -----
// C[M,N] = A[M,K] * B^T; A [M,K], B [N,K], row-major K-major half.
// CTA tile 128x128, 4 warps with 64x64 warp tiles (each fragment loaded by
// only 2 warps -> 0.25 LDSM/MMA), BK=64, 3-stage cp.async, 2 CTAs/SM.
// EPI: 0 = fp32 direct, 1 = fp16 staged (+ optional V^T side-write for z==2),
//      2 = mask+scale fp32 direct (scores epilogue).
constexpr int BM = 128, BN = 128, BK = 64, STG = 3;
constexpr int NT = 128;                         // threads per CTA
constexpr int TSZ = 128 * 128;                  // bytes per (A or B) tile stage
constexpr int GSMEM = STG * 2 * TSZ;            // 98304 B; 2 CTAs fit in 228KB
constexpr int SP = 65;                          // fp32 staging stride (pad)

template <int EPI>
__global__ __launch_bounds__(NT, 2) void gemm_h(
    const __half* __restrict__ A, const __half* __restrict__ Bm,
    void* __restrict__ Cv, const int* __restrict__ mask,
    __half* __restrict__ vt,
    int N, int K, long long sA, long long sB, long long sC)
{
    A  += (long long)blockIdx.z * sA;
    Bm += (long long)blockIdx.z * sB;

    extern __shared__ __half smh[];
    const uint32_t sbase = (uint32_t)__cvta_generic_to_shared(smh);

    const int t   = threadIdx.x;
    const int w   = t >> 5;          // 0..3
    const int ln  = t & 31;
    const int wm  = (w >> 1) * 64;   // 2 warps along M
    const int wn  = (w & 1) * 64;    // 2 warps along N
    const int bm  = blockIdx.y * BM;
    const int bn  = blockIdx.x * BN;

    // swizzled stage loader: tile = 128 rows x 128B, chunk c (16B) at
    // r*128 + ((c ^ (r&7))<<4). 1024 chunks per tile, 8 per thread.
    auto load_stage = [&](int s, int k0) {
        uint32_t ab = sbase + (uint32_t)(s * 2 * TSZ);
        uint32_t bb = ab + TSZ;
#pragma unroll
        for (int i = 0; i < 8; i++) {
            int idx = t + i * NT;
            int r = idx >> 3, c = idx & 7;
            uint32_t off = (uint32_t)(r * 128) + (uint32_t)(((c ^ (r & 7)) << 4));
            cp16(ab + off, &A[(long long)(bm + r) * K + k0 + c * 8]);
        }
#pragma unroll
        for (int i = 0; i < 8; i++) {
            int idx = t + i * NT;
            int r = idx >> 3, c = idx & 7;
            uint32_t off = (uint32_t)(r * 128) + (uint32_t)(((c ^ (r & 7)) << 4));
            cp16(bb + off, &Bm[(long long)(bn + r) * K + k0 + c * 8]);
        }
    };

    float acc[4][8][4];
#pragma unroll
    for (int i = 0; i < 4; i++)
#pragma unroll
        for (int j = 0; j < 8; j++)
#pragma unroll
            for (int e = 0; e < 4; e++) acc[i][j][e] = 0.0f;

    const int r16  = ln & 15;
    const int cbit = ln >> 4;
    const int x7   = ln & 7;

    // one K=16 step: 4 A LDSM (64 rows) + 4 B LDSM (64 n) -> 32 mma
    auto compute_ks = [&](uint32_t aSt, uint32_t bSt, int ks) {
        const uint32_t xr = (uint32_t)(((2 * ks + cbit) ^ x7) << 4);
        uint32_t a[4][4];
#pragma unroll
        for (int mi = 0; mi < 4; mi++)
            ldsm4(a[mi], aSt + (uint32_t)((wm + mi * 16 + r16) * 128) + xr);
        uint32_t bq[4][4];
#pragma unroll
        for (int nb = 0; nb < 4; nb++)
            ldsm4(bq[nb], bSt + (uint32_t)((wn + nb * 16 + r16) * 128) + xr);
#pragma unroll
        for (int mi = 0; mi < 4; mi++)
#pragma unroll
            for (int nb = 0; nb < 4; nb++) {
                mma16816(acc[mi][2 * nb],     a[mi], bq[nb][0], bq[nb][2]);
                mma16816(acc[mi][2 * nb + 1], a[mi], bq[nb][1], bq[nb][3]);
            }
    };

    const int KT = K / BK;

#pragma unroll
    for (int s = 0; s < STG - 1; s++) { load_stage(s, s * BK); cp_commit(); }

    for (int kt = 0; kt < KT; kt++) {
        asm volatile("cp.async.wait_group 1;\n" ::: "memory");
        __syncthreads();

        const uint32_t aSt = sbase + (uint32_t)((kt % STG) * 2 * TSZ);
        const uint32_t bSt = aSt + TSZ;

        compute_ks(aSt, bSt, 0);           // tensor work first

        int f = kt + STG - 1;
        if (f < KT) load_stage(f % STG, f * BK);
        cp_commit();

        compute_ks(aSt, bSt, 1);
        compute_ks(aSt, bSt, 2);
        compute_ks(aSt, bSt, 3);
    }

    const int fr = ln >> 2;
    const int fc = (ln & 3) * 2;

    if constexpr (EPI == 0) {
        float* Cf = (float*)Cv + (long long)blockIdx.z * sC;
#pragma unroll
        for (int mi = 0; mi < 4; mi++)
#pragma unroll
            for (int nj = 0; nj < 8; nj++) {
                long long row = bm + wm + mi * 16 + fr;
                long long col = bn + wn + nj * 8 + fc;
                float2 v0 = make_float2(acc[mi][nj][0], acc[mi][nj][1]);
                float2 v1 = make_float2(acc[mi][nj][2], acc[mi][nj][3]);
                *(float2*)&Cf[row * N + col]       = v0;
                *(float2*)&Cf[(row + 8) * N + col] = v1;
            }
    } else if constexpr (EPI == 2) {
        float* Cf = (float*)Cv + (long long)blockIdx.z * sC;
        const int* Mb = mask + (long long)blockIdx.z * sC;
#pragma unroll
        for (int mi = 0; mi < 4; mi++)
#pragma unroll
            for (int nj = 0; nj < 8; nj++) {
                long long row = bm + wm + mi * 16 + fr;
                long long col = bn + wn + nj * 8 + fc;
                long long g0 = row * N + col, g1 = (row + 8) * N + col;
                int2 m0 = *(const int2*)&Mb[g0];
                int2 m1 = *(const int2*)&Mb[g1];
                float2 v0, v1;
                v0.x = (m0.x == 1) ? -1e9f : acc[mi][nj][0] * 0.125f;
                v0.y = (m0.y == 1) ? -1e9f : acc[mi][nj][1] * 0.125f;
                v1.x = (m1.x == 1) ? -1e9f : acc[mi][nj][2] * 0.125f;
                v1.y = (m1.y == 1) ? -1e9f : acc[mi][nj][3] * 0.125f;
                *(float2*)&Cf[g0] = v0;
                *(float2*)&Cf[g1] = v1;
            }
    } else {
        // EPI == 1: stage fp32 accs in (reused) pipeline smem, 64x(64+pad)/warp
        __syncthreads();   // all warps done with LDSM reads of pipeline smem
        float* stg = (float*)smh + (size_t)w * (64 * SP);
#pragma unroll
        for (int mi = 0; mi < 4; mi++)
#pragma unroll
            for (int nj = 0; nj < 8; nj++) {
                int r0 = mi * 16 + fr, c0 = nj * 8 + fc;
                stg[r0 * SP + c0]           = acc[mi][nj][0];
                stg[r0 * SP + c0 + 1]       = acc[mi][nj][1];
                stg[(r0 + 8) * SP + c0]     = acc[mi][nj][2];
                stg[(r0 + 8) * SP + c0 + 1] = acc[mi][nj][3];
            }
        __syncwarp();
        if (vt != nullptr && blockIdx.z == 2) {
            // V^T side-write: Vt[batch][f][s] = V[s][f], coalesced half2 on s
            const int batch = bm / SEQ;
            const int sloc  = (bm % SEQ) + wm + 2 * ln;
            __half* Vtb = vt + (size_t)batch * DMODEL * SEQ;
#pragma unroll
            for (int c = 0; c < 64; c++) {
                float v0 = stg[(2 * ln) * SP + c];
                float v1 = stg[(2 * ln + 1) * SP + c];
                __half2 h = __floats2half2_rn(v0, v1);
                *(__half2*)&Vtb[(long long)(bn + wn + c) * SEQ + sloc] = h;
            }
        } else {
            __half* Ch = (__half*)Cv + (long long)blockIdx.z * sC;
#pragma unroll
            for (int it = 0; it < 64; it++) {
                // row = it, cols 2*ln..2*ln+1 -> coalesced half2 stores
                float va = stg[it * SP + 2 * ln];
                float vb = stg[it * SP + 2 * ln + 1];
                __half2 h = __floats2half2_rn(va, vb);
                *(__half2*)&Ch[(long long)(bm + wm + it) * N + bn + wn + 2 * ln] = h;
            }
        }
    }
}

// ---------------- fused fp32 -> fp16 converts ---------------------------------
__global__ __launch_bounds__(256) void f2h3(
    const float* __restrict__ x0, const float* __restrict__ x1,
    const float* __restrict__ x2, __half* __restrict__ y, int n4)
{
    const float* x = (blockIdx.y == 0) ? x0 : (blockIdx.y == 1) ? x1 : x2;
    __half* yo = y + (size_t)blockIdx.y * MT * DMODEL;
    int i = blockIdx.x * 256 + threadIdx.x;
    if (i < n4) {
        float4 v = ((const float4*)x)[i];
        __half2 a = __floats2half2_rn(v.x, v.y);
        __half2 b = __floats2half2_rn(v.z, v.w);
        uint2 u; u.x = *(uint32_t*)&a; u.y = *(uint32_t*)&b;
        ((uint2*)yo)[i] = u;
    }
}

__global__ __launch_bounds__(256) void f2h4(
    const float* __restrict__ x0, const float* __restrict__ x1,
    const float* __restrict__ x2, const float* __restrict__ x3,
    __half* __restrict__ y, int n4)
{
    const float* x = (blockIdx.y == 0) ? x0 : (blockIdx.y == 1) ? x1
                   : (blockIdx.y == 2) ? x2 : x3;
    __half* yo = y + (size_t)blockIdx.y * DMODEL * DMODEL;
    int i = blockIdx.x * 256 + threadIdx.x;
    if (i < n4) {
        float4 v = ((const float4*)x)[i];
        __half2 a = __floats2half2_rn(v.x, v.y);
        __half2 b = __floats2half2_rn(v.z, v.w);
        uint2 u; u.x = *(uint32_t*)&a; u.y = *(uint32_t*)&b;
        ((uint2*)yo)[i] = u;
    }
}

// ---------------- softmax over pre-masked scaled rows -> fp16 (vectorized) ----
__global__ __launch_bounds__(256) void softmax_rows(
    const float* __restrict__ S, __half* __restrict__ Ao)
{
    const long long row = blockIdx.x;
    const float4* sr4 = (const float4*)(S + row * (long long)SEQ);
    uint2* ar2 = (uint2*)(Ao + row * (long long)SEQ);
    const int t = threadIdx.x;

    float4 q0 = sr4[t];
    float4 q1 = sr4[t + 256];
    float v[8] = {q0.x, q0.y, q0.z, q0.w, q1.x, q1.y, q1.z, q1.w};

    float mx = -3.0e38f;
#pragma unroll
    for (int i = 0; i < 8; i++) mx = fmaxf(mx, v[i]);

    __shared__ float red[8];
#pragma unroll
    for (int o = 16; o; o >>= 1) mx = fmaxf(mx, __shfl_xor_sync(~0u, mx, o));
    if ((t & 31) == 0) red[t >> 5] = mx;
    __syncthreads();
    mx = red[0];
#pragma unroll
    for (int i = 1; i < 8; i++) mx = fmaxf(mx, red[i]);

    float sum = 0.f;
#pragma unroll
    for (int i = 0; i < 8; i++) {
        v[i] = exp2f((v[i] - mx) * 1.4426950408889634f);
        sum += v[i];
    }
#pragma unroll
    for (int o = 16; o; o >>= 1) sum += __shfl_xor_sync(~0u, sum, o);
    __syncthreads();
    if ((t & 31) == 0) red[t >> 5] = sum;
    __syncthreads();
    sum = 0.f;
#pragma unroll
    for (int i = 0; i < 8; i++) sum += red[i];
    const float inv = 1.0f / sum;

    __half2 h0 = __floats2half2_rn(v[0] * inv, v[1] * inv);
    __half2 h1 = __floats2half2_rn(v[2] * inv, v[3] * inv);
    __half2 h2 = __floats2half2_rn(v[4] * inv, v[5] * inv);
    __half2 h3 = __floats2half2_rn(v[6] * inv, v[7] * inv);
    uint2 u0, u1;
    u0.x = *(uint32_t*)&h0; u0.y = *(uint32_t*)&h1;
    u1.x = *(uint32_t*)&h2; u1.y = *(uint32_t*)&h3;
    ar2[t]       = u0;
    ar2[t + 256] = u1;
}

// ---------------- residual add + LayerNorm (float4 single pass) ---------------
__global__ __launch_bounds__(256) void add_layernorm(
    const float* __restrict__ P, const float* __restrict__ R,
    const float* __restrict__ gamma, const float* __restrict__ beta,
    float* __restrict__ O)
{
    const long long row = blockIdx.x;
    const float4* pr4 = (const float4*)(P + row * (long long)DMODEL);
    const float4* rr4 = (const float4*)(R + row * (long long)DMODEL);
    float4* o4 = (float4*)(O + row * (long long)DMODEL);
    const int t = threadIdx.x;

    float4 p = pr4[t], r = rr4[t];
    float x[4] = {p.x + r.x, p.y + r.y, p.z + r.z, p.w + r.w};
    float s = x[0] + x[1] + x[2] + x[3];

    __shared__ float red[8];
#pragma unroll
    for (int o = 16; o; o >>= 1) s += __shfl_xor_sync(~0u, s, o);
    if ((t & 31) == 0) red[t >> 5] = s;
    __syncthreads();
    s = 0.f;
#pragma unroll
    for (int i = 0; i < 8; i++) s += red[i];
    const float mu = s * (1.0f / DMODEL);

    float vq = 0.f;
#pragma unroll
    for (int i = 0; i < 4; i++) {
        float d = x[i] - mu;
        vq += d * d;
    }
#pragma unroll
    for (int o = 16; o; o >>= 1) vq += __shfl_xor_sync(~0u, vq, o);
    __syncthreads();
    if ((t & 31) == 0) red[t >> 5] = vq;
    __syncthreads();
    vq = 0.f;
#pragma unroll
    for (int i = 0; i < 8; i++) vq += red[i];
    const float rs = rsqrtf(vq * (1.0f / DMODEL) + 1e-5f);

    float4 g = ((const float4*)gamma)[t];
    float4 b = ((const float4*)beta)[t];
    float4 o;
    o.x = (x[0] - mu) * rs * g.x + b.x;
    o.y = (x[1] - mu) * rs * g.y + b.y;
    o.z = (x[2] - mu) * rs * g.z + b.z;
    o.w = (x[3] - mu) * rs * g.w + b.w;
    o4[t] = o;
}

// ---------------- launch ------------------------------------------------------
extern "C" void kernel_launch(void* const* d_in, const int* in_sizes, int n_in,
                              void* d_out, int out_size)
{
    (void)in_sizes; (void)n_in; (void)out_size;
    const float* inQ  = (const float*)d_in[0];
    const float* inK  = (const float*)d_in[1];
    const float* inV  = (const float*)d_in[2];
    const int*   mask = (const int*)  d_in[3];
    const float* WQ   = (const float*)d_in[4];
    const float* WK   = (const float*)d_in[5];
    const float* WV   = (const float*)d_in[6];
    const float* WO   = (const float*)d_in[7];
    const float* gam  = (const float*)d_in[8];
    const float* bet  = (const float*)d_in[9];
    float* out = (float*)d_out;

    void *pIN, *pW4, *pQKV, *pVt, *pA, *pWv, *pS, *pP;
    cudaGetSymbolAddress(&pIN,  g_hIN);
    cudaGetSymbolAddress(&pW4,  g_hW4);
    cudaGetSymbolAddress(&pQKV, g_hQKV);
    cudaGetSymbolAddress(&pVt,  g_hVt);
    cudaGetSymbolAddress(&pA,   g_hA);
    cudaGetSymbolAddress(&pWv,  g_hWv);
    cudaGetSymbolAddress(&pS,   g_S);
    cudaGetSymbolAddress(&pP,   g_P);
    __half* hIN  = (__half*)pIN;
    __half* hW   = (__half*)pW4;
    __half* hWO  = hW + 3 * (size_t)DMODEL * DMODEL;
    __half* hQKV = (__half*)pQKV;
    __half* hQ   = hQKV;
    __half* hK   = hQKV + (size_t)MT * DMODEL;
    __half* hVt  = (__half*)pVt;
    __half* hA   = (__half*)pA;
    __half* hWv  = (__half*)pWv;
    float*  S    = (float*)pS;
    float*  P    = (float*)pP;

    cudaFuncSetAttribute(gemm_h<0>,
                         cudaFuncAttributeMaxDynamicSharedMemorySize, GSMEM);
    cudaFuncSetAttribute(gemm_h<1>,
                         cudaFuncAttributeMaxDynamicSharedMemorySize, GSMEM);
    cudaFuncSetAttribute(gemm_h<2>,
                         cudaFuncAttributeMaxDynamicSharedMemorySize, GSMEM);

    const dim3 blk(NT);
    const long long sQK = (long long)SEQ * DMODEL;    // per-batch Q/K stride
    const long long sSS = (long long)SEQ * SEQ;       // per-batch scores stride
    const long long sVT = (long long)DMODEL * SEQ;    // per-batch V^T stride
    const long long sIN = (long long)MT * DMODEL;     // per-matrix input stride
    const long long sW  = (long long)DMODEL * DMODEL; // per-matrix weight stride

    // launch 1-2: fused fp32 -> fp16 converts
    const int nBig4 = MT * DMODEL / 4;
    const int nW4   = DMODEL * DMODEL / 4;
    f2h3<<<dim3((nBig4 + 255) / 256, 3), 256>>>(inQ, inK, inV, hIN, nBig4);
    f2h4<<<dim3((nW4 + 255) / 256, 4), 256>>>(WQ, WK, WV, WO, hW, nW4);

    // launch 3: batched Q/K/V projections (z=0..2); z==2 writes V^T directly
    gemm_h<1><<<dim3(DMODEL / BN, MT / BM, 3), blk, GSMEM>>>(
        hIN, hW, hQKV, nullptr, hVt, DMODEL, DMODEL, sIN, sW, sIN);

    // launch 4 (ncu slot): scores = Q*K^T with fused mask+scale -> fp32
    gemm_h<2><<<dim3(SEQ / BN, SEQ / BM, NB), blk, GSMEM>>>(
        hQ, hK, S, mask, nullptr, SEQ, DMODEL, sQK, sQK, sSS);

    // launch 5: softmax over pre-masked rows -> fp16 attn
    softmax_rows<<<NB * SEQ, 256>>>(S, hA);

    // launch 6: attn @ V = A * (V^T)^T (NT with B = V^T) -> half
    gemm_h<1><<<dim3(DMODEL / BN, SEQ / BM, NB), blk, GSMEM>>>(
        hA, hVt, hWv, nullptr, nullptr, DMODEL, SEQ, sSS, sVT, sQK);

    // launch 7: out proj: W * WO^T (NT) -> fp32
    gemm_h<0><<<dim3(DMODEL / BN, MT / BM, 1), blk, GSMEM>>>(
        hWv, hWO, P, nullptr, nullptr, DMODEL, DMODEL, 0, 0, 0);

    // launch 8: residual + layernorm -> d_out
    add_layernorm<<<MT, 256>>>(P, inQ, gam, bet, out);
}